// round 9
// baseline (speedup 1.0000x reference)
#include <cuda_runtime.h>
#include <cuda_fp16.h>

// Problem constants (fixed by setup_inputs)
static constexpr int N_NODES = 100000;
static constexpr int N_EDGES = 1600000;
static constexpr int BLD_GRID = 592;   // 4 blocks/SM x 148 SMs -> always co-resident
static constexpr int BLD_T = 256;
static constexpr int NB2 = (N_NODES + BLD_T - 1) / BLD_T;  // 391 scan tiles

// ---------------- scratch (static __device__, allocation-free) ----------------
__device__ int   g_cnt[N_NODES];
__device__ int   g_row[N_NODES + 1];
__device__ int   g_blkagg[NB2];
__device__ volatile int g_blkflag[NB2];
__device__ int   g_col[N_EDGES];
__device__ unsigned long long g_ep[N_EDGES];   // packed s(17) | d(17) | pos
__device__ float g_dinv[N_NODES];
__device__ float g_t1[N_NODES * 16];           // x @ W1 (UNscaled)
__device__ float g_h1[N_NODES * 16];           // dinv * relu(...)  (pre-scaled)
__device__ unsigned int g_h2h[N_NODES * 32];   // fp16 half2 h2'
__device__ float g_a3[N_NODES * 64];
__device__ int   g_is64;
// epoch-based global barrier state (monotone; safe across graph replays)
__device__ int   g_bcnt[4];
__device__ volatile int g_brel[4];

// ---------------- f32x2 packed-FMA helpers (sm_103a) ----------------
typedef unsigned long long ull;
__device__ __forceinline__ ull pack2(float v) {
    ull r; asm("mov.b64 %0, {%1, %1};" : "=l"(r) : "f"(v)); return r;
}
__device__ __forceinline__ void ffma2(ull& d, ull a, ull b) {
    asm("fma.rn.f32x2 %0, %1, %2, %0;" : "+l"(d) : "l"(a), "l"(b));
}
__device__ __forceinline__ float2 unpack2(ull v) {
    float2 r; asm("mov.b64 {%0, %1}, %2;" : "=f"(r.x), "=f"(r.y) : "l"(v)); return r;
}

// ---------------- device-wide barrier (all BLD_GRID blocks resident) ----------
__device__ __forceinline__ void gbar(int k) {
    __syncthreads();
    if (threadIdx.x == 0) {
        __threadfence();
        int old = atomicAdd(&g_bcnt[k], 1);
        int target = old / BLD_GRID + 1;
        if ((old % BLD_GRID) == BLD_GRID - 1) atomicAdd((int*)&g_brel[k], 1);
        while (g_brel[k] < target) { }
        __threadfence();
    }
    __syncthreads();
}

// ---------------- mega build kernel: zero -> gemm1 -> count -> scan -> fill ----
__global__ void __launch_bounds__(BLD_T, 4) k_build(const void* e,
                                                    const float* __restrict__ x,
                                                    const float* __restrict__ W1) {
    __shared__ __align__(16) float sW[128 * 16];  // 8KB
    __shared__ int ss[BLD_T];
    __shared__ int sPre;
    const int gsz  = BLD_GRID * BLD_T;
    const int gtid = blockIdx.x * BLD_T + threadIdx.x;

    // ---- Phase A: zero counters/flags, dtype detect, gemm1 (graph-independent)
    for (int i = gtid; i < N_NODES; i += gsz) g_cnt[i] = 0;
    for (int i = gtid; i < NB2; i += gsz) g_blkflag[i] = 0;
    if (gtid == 0) {
        const unsigned int* eu = (const unsigned int*)e;
        int is64 = 1;
        for (int k = 0; k < 64; k++) {
            if (eu[2 * k + 1] != 0u) { is64 = 0; break; }
        }
        g_is64 = is64;
    }
    for (int idx = threadIdx.x; idx < 128 * 16; idx += BLD_T) sW[idx] = W1[idx];
    __syncthreads();
    for (int n = gtid; n < N_NODES; n += gsz) {
        const float4* xr = (const float4*)(x + (size_t)n * 128);
        ull acc[8];
#pragma unroll
        for (int q = 0; q < 8; q++) acc[q] = 0ull;
#pragma unroll 4
        for (int k4 = 0; k4 < 32; k4++) {
            float4 v = __ldg(&xr[k4]);
#pragma unroll
            for (int kk = 0; kk < 4; kk++) {
                float xv = (kk == 0) ? v.x : (kk == 1) ? v.y : (kk == 2) ? v.z : v.w;
                ull av = pack2(xv);
                const ulonglong2* wr = (const ulonglong2*)(sW + (4 * k4 + kk) * 16);
                ulonglong2 w01 = wr[0], w23 = wr[1], w45 = wr[2], w67 = wr[3];
                ffma2(acc[0], av, w01.x); ffma2(acc[1], av, w01.y);
                ffma2(acc[2], av, w23.x); ffma2(acc[3], av, w23.y);
                ffma2(acc[4], av, w45.x); ffma2(acc[5], av, w45.y);
                ffma2(acc[6], av, w67.x); ffma2(acc[7], av, w67.y);
            }
        }
        float4* o = (float4*)(g_t1 + (size_t)n * 16);
#pragma unroll
        for (int q = 0; q < 4; q++) {
            float2 p0 = unpack2(acc[2 * q]), p1 = unpack2(acc[2 * q + 1]);
            o[q] = make_float4(p0.x, p0.y, p1.x, p1.y);
        }
    }
    gbar(0);

    // ---- Phase B: decode + degree count; atomic return value = within-row pos
    {
        int is64 = g_is64;
        for (int i = gtid; i < N_EDGES; i += gsz) {
            int s, d;
            if (is64) {
                const long long* p = (const long long*)e;
                s = (int)p[i];
                d = (int)p[N_EDGES + i];
            } else {
                const int* p = (const int*)e;
                s = p[i];
                d = p[N_EDGES + i];
            }
            if ((unsigned)d >= (unsigned)N_NODES || (unsigned)s >= (unsigned)N_NODES) {
                g_ep[i] = ~0ull;
                continue;
            }
            int pos = atomicAdd(&g_cnt[d], 1);
            g_ep[i] = (ull)(unsigned)s | ((ull)(unsigned)d << 17) | ((ull)(unsigned)pos << 34);
        }
    }
    gbar(1);

    // ---- Phase C: exclusive scan over counts (tiles of 256) + dinv
    if (blockIdx.x < NB2) {
        int bid = blockIdx.x;
        int i = bid * BLD_T + threadIdx.x;
        int v = (i < N_NODES) ? g_cnt[i] : 0;
        if (i < N_NODES) g_dinv[i] = rsqrtf((float)(v + 1));
        ss[threadIdx.x] = v;
        __syncthreads();
        for (int d = 1; d < BLD_T; d <<= 1) {
            int t = (threadIdx.x >= d) ? ss[threadIdx.x - d] : 0;
            __syncthreads();
            ss[threadIdx.x] += t;
            __syncthreads();
        }
        if (threadIdx.x == BLD_T - 1) {
            g_blkagg[bid] = ss[BLD_T - 1];
            __threadfence();
            g_blkflag[bid] = 1;
        }
        if (threadIdx.x == 0) sPre = 0;
        __syncthreads();
        int p = 0;
        for (int b = threadIdx.x; b < bid; b += BLD_T) {
            while (g_blkflag[b] == 0) { }
            p += *((volatile int*)&g_blkagg[b]);
        }
        if (p) atomicAdd(&sPre, p);
        __syncthreads();
        if (i < N_NODES) g_row[i] = sPre + ss[threadIdx.x] - v;
        if (bid == 0 && threadIdx.x == 0) g_row[N_NODES] = N_EDGES;
    }
    gbar(2);

    // ---- Phase D: atomic-free CSR fill
    for (int i = gtid; i < N_EDGES; i += gsz) {
        ull ep = g_ep[i];
        int d = (int)((ep >> 17) & 0x1FFFFull);
        if (d >= N_NODES) continue;
        int s   = (int)(ep & 0x1FFFFull);
        int pos = (int)(ep >> 34);
        g_col[g_row[d] + pos] = s;
    }
}

// ---------------- agg 16-wide (+b1+relu): h1' = di·relu(di·S + b1) -------------
// S = Σ_src dinv[s]·t1[s] + di·t1[i]   (t1 is UNscaled; dinv gathered per edge)
__global__ void __launch_bounds__(256) k_agg16(const float* __restrict__ bias) {
    const float4* __restrict__ t4 = (const float4*)g_t1;
    float4* __restrict__ o4 = (float4*)g_h1;
    int g = threadIdx.x & 3;
    int i = blockIdx.x * 64 + (threadIdx.x >> 2);
    if (i >= N_NODES) return;

    float di = g_dinv[i];
    float4 sv = t4[(size_t)i * 4 + g];
    float4 acc = make_float4(di * sv.x, di * sv.y, di * sv.z, di * sv.w);
    int beg = g_row[i], end = g_row[i + 1];
    int j = beg;
    for (; j + 3 < end; j += 4) {
        int s0 = __ldg(&g_col[j]);
        int s1 = __ldg(&g_col[j + 1]);
        int s2 = __ldg(&g_col[j + 2]);
        int s3 = __ldg(&g_col[j + 3]);
        float w0 = __ldg(&g_dinv[s0]);
        float w1 = __ldg(&g_dinv[s1]);
        float w2 = __ldg(&g_dinv[s2]);
        float w3 = __ldg(&g_dinv[s3]);
        float4 v0 = __ldg(&t4[(size_t)s0 * 4 + g]);
        float4 v1 = __ldg(&t4[(size_t)s1 * 4 + g]);
        float4 v2 = __ldg(&t4[(size_t)s2 * 4 + g]);
        float4 v3 = __ldg(&t4[(size_t)s3 * 4 + g]);
        acc.x = fmaf(w0, v0.x, fmaf(w1, v1.x, fmaf(w2, v2.x, fmaf(w3, v3.x, acc.x))));
        acc.y = fmaf(w0, v0.y, fmaf(w1, v1.y, fmaf(w2, v2.y, fmaf(w3, v3.y, acc.y))));
        acc.z = fmaf(w0, v0.z, fmaf(w1, v1.z, fmaf(w2, v2.z, fmaf(w3, v3.z, acc.z))));
        acc.w = fmaf(w0, v0.w, fmaf(w1, v1.w, fmaf(w2, v2.w, fmaf(w3, v3.w, acc.w))));
    }
    for (; j < end; j++) {
        int s = __ldg(&g_col[j]);
        float w = __ldg(&g_dinv[s]);
        float4 v = __ldg(&t4[(size_t)s * 4 + g]);
        acc.x = fmaf(w, v.x, acc.x); acc.y = fmaf(w, v.y, acc.y);
        acc.z = fmaf(w, v.z, acc.z); acc.w = fmaf(w, v.w, acc.w);
    }
    float4 b = ((const float4*)bias)[g];
    float4 r;
    r.x = di * fmaxf(fmaf(di, acc.x, b.x), 0.f);
    r.y = di * fmaxf(fmaf(di, acc.y, b.y), 0.f);
    r.z = di * fmaxf(fmaf(di, acc.z, b.z), 0.f);
    r.w = di * fmaxf(fmaf(di, acc.w, b.w), 0.f);
    o4[(size_t)i * 4 + g] = r;
}

// ---------------- fused: agg(h1') 16-wide -> GEMM 16->64 -> fp16 h2' -----------
__global__ void __launch_bounds__(256) k_aggemm2(const float* __restrict__ W2,
                                                 const float* __restrict__ b2) {
    __shared__ __align__(16) float sW[16 * 64];
    __shared__ __align__(16) float sB[64];
    for (int idx = threadIdx.x; idx < 16 * 64; idx += 256) sW[idx] = W2[idx];
    if (threadIdx.x < 64) sB[threadIdx.x] = b2[threadIdx.x];
    __syncthreads();

    const float4* __restrict__ t4 = (const float4*)g_h1;
    int g = threadIdx.x & 3;
    int i = blockIdx.x * 64 + (threadIdx.x >> 2);
    if (i >= N_NODES) return;

    float4 acc = t4[(size_t)i * 4 + g];
    int beg = g_row[i], end = g_row[i + 1];
    int j = beg;
    for (; j + 3 < end; j += 4) {
        int s0 = __ldg(&g_col[j]);
        int s1 = __ldg(&g_col[j + 1]);
        int s2 = __ldg(&g_col[j + 2]);
        int s3 = __ldg(&g_col[j + 3]);
        float4 v0 = __ldg(&t4[(size_t)s0 * 4 + g]);
        float4 v1 = __ldg(&t4[(size_t)s1 * 4 + g]);
        float4 v2 = __ldg(&t4[(size_t)s2 * 4 + g]);
        float4 v3 = __ldg(&t4[(size_t)s3 * 4 + g]);
        acc.x += (v0.x + v1.x) + (v2.x + v3.x);
        acc.y += (v0.y + v1.y) + (v2.y + v3.y);
        acc.z += (v0.z + v1.z) + (v2.z + v3.z);
        acc.w += (v0.w + v1.w) + (v2.w + v3.w);
    }
    for (; j < end; j++) {
        int s = __ldg(&g_col[j]);
        float4 v = __ldg(&t4[(size_t)s * 4 + g]);
        acc.x += v.x; acc.y += v.y; acc.z += v.z; acc.w += v.w;
    }
    float di = g_dinv[i];
    float4 mya = make_float4(di * acc.x, di * acc.y, di * acc.z, di * acc.w);

    float a[16];
    int base = threadIdx.x & 31 & ~3;
#pragma unroll
    for (int q = 0; q < 4; q++) {
        int src = base + q;
        a[4 * q + 0] = __shfl_sync(0xffffffffu, mya.x, src);
        a[4 * q + 1] = __shfl_sync(0xffffffffu, mya.y, src);
        a[4 * q + 2] = __shfl_sync(0xffffffffu, mya.z, src);
        a[4 * q + 3] = __shfl_sync(0xffffffffu, mya.w, src);
    }

    ull oacc[8];
    const ull* sBu = (const ull*)sB;
#pragma unroll
    for (int m = 0; m < 8; m++) oacc[m] = sBu[g * 8 + m];
#pragma unroll
    for (int k = 0; k < 16; k++) {
        ull av = pack2(a[k]);
        const ull* wr = (const ull*)(sW + k * 64) + g * 8;
#pragma unroll
        for (int m = 0; m < 8; m++) ffma2(oacc[m], av, wr[m]);
    }
    unsigned int hs[8];
#pragma unroll
    for (int m = 0; m < 8; m++) {
        float2 pv = unpack2(oacc[m]);
        __half2 h = __floats2half2_rn(fmaxf(di * pv.x, 0.f), fmaxf(di * pv.y, 0.f));
        hs[m] = *(const unsigned int*)&h;
    }
    uint4* o = (uint4*)(g_h2h + (size_t)i * 32 + g * 8);
    o[0] = make_uint4(hs[0], hs[1], hs[2], hs[3]);
    o[1] = make_uint4(hs[4], hs[5], hs[6], hs[7]);
}

// ---------------- fp16 aggregation (64-wide): a3 = di·(h2'[i] + Σ h2'[src]) ----
__global__ void __launch_bounds__(256) k_agg64h() {
    const uint2* __restrict__ t = (const uint2*)g_h2h;
    int g = threadIdx.x & 15;
    int i = blockIdx.x * 16 + (threadIdx.x >> 4);
    if (i >= N_NODES) return;

    uint2 sv = __ldg(&t[(size_t)i * 16 + g]);
    float2 lo = __half22float2(*(const __half2*)&sv.x);
    float2 hi = __half22float2(*(const __half2*)&sv.y);
    float4 acc = make_float4(lo.x, lo.y, hi.x, hi.y);

    int beg = g_row[i], end = g_row[i + 1];
    int j = beg;
    for (; j + 3 < end; j += 4) {
        int s0 = __ldg(&g_col[j]);
        int s1 = __ldg(&g_col[j + 1]);
        int s2 = __ldg(&g_col[j + 2]);
        int s3 = __ldg(&g_col[j + 3]);
        uint2 v0 = __ldg(&t[(size_t)s0 * 16 + g]);
        uint2 v1 = __ldg(&t[(size_t)s1 * 16 + g]);
        uint2 v2 = __ldg(&t[(size_t)s2 * 16 + g]);
        uint2 v3 = __ldg(&t[(size_t)s3 * 16 + g]);
        float2 a0 = __half22float2(*(const __half2*)&v0.x), b0 = __half22float2(*(const __half2*)&v0.y);
        float2 a1 = __half22float2(*(const __half2*)&v1.x), b1 = __half22float2(*(const __half2*)&v1.y);
        float2 a2 = __half22float2(*(const __half2*)&v2.x), b2 = __half22float2(*(const __half2*)&v2.y);
        float2 a3 = __half22float2(*(const __half2*)&v3.x), b3 = __half22float2(*(const __half2*)&v3.y);
        acc.x += (a0.x + a1.x) + (a2.x + a3.x);
        acc.y += (a0.y + a1.y) + (a2.y + a3.y);
        acc.z += (b0.x + b1.x) + (b2.x + b3.x);
        acc.w += (b0.y + b1.y) + (b2.y + b3.y);
    }
    for (; j < end; j++) {
        int s = __ldg(&g_col[j]);
        uint2 v = __ldg(&t[(size_t)s * 16 + g]);
        float2 a = __half22float2(*(const __half2*)&v.x);
        float2 b = __half22float2(*(const __half2*)&v.y);
        acc.x += a.x; acc.y += a.y; acc.z += b.x; acc.w += b.y;
    }
    float di = g_dinv[i];
    ((float4*)g_a3)[(size_t)i * 16 + g] =
        make_float4(di * acc.x, di * acc.y, di * acc.z, di * acc.w);
}

// ---------------- fused layer 3 + FC (f32x2) -----------------------------------
__global__ void __launch_bounds__(256) k_final(const float* __restrict__ W3,
                                               const float* __restrict__ b3,
                                               const float* __restrict__ Wfc,
                                               const float* __restrict__ bfc,
                                               float* __restrict__ out) {
    __shared__ __align__(16) float sW[64 * 128];
    __shared__ __align__(16) float sB[128];
    __shared__ __align__(16) float sF[128];
    for (int idx = threadIdx.x; idx < 64 * 128; idx += 256) sW[idx] = W3[idx];
    if (threadIdx.x < 128) {
        sB[threadIdx.x] = b3[threadIdx.x];
        sF[threadIdx.x] = Wfc[threadIdx.x];
    }
    __syncthreads();
    int n = blockIdx.x * 256 + threadIdx.x;
    if (n >= N_NODES) return;

    float a[64];
    const float4* ar = (const float4*)(g_a3 + (size_t)n * 64);
#pragma unroll
    for (int k4 = 0; k4 < 16; k4++) {
        float4 v = __ldg(&ar[k4]);
        a[4 * k4 + 0] = v.x; a[4 * k4 + 1] = v.y;
        a[4 * k4 + 2] = v.z; a[4 * k4 + 3] = v.w;
    }

    float o = 0.f;
#pragma unroll 1
    for (int j = 0; j < 128; j += 8) {
        const ulonglong2* bi = (const ulonglong2*)(sB + j);
        ulonglong2 b01 = bi[0], b23 = bi[1];
        ull acc0 = b01.x, acc1 = b01.y, acc2 = b23.x, acc3 = b23.y;
#pragma unroll
        for (int k = 0; k < 64; k++) {
            ull av = pack2(a[k]);
            const ulonglong2* w = (const ulonglong2*)(sW + k * 128 + j);
            ulonglong2 w01 = w[0], w23 = w[1];
            ffma2(acc0, av, w01.x);
            ffma2(acc1, av, w01.y);
            ffma2(acc2, av, w23.x);
            ffma2(acc3, av, w23.y);
        }
        float2 p0 = unpack2(acc0), p1 = unpack2(acc1);
        float2 p2 = unpack2(acc2), p3 = unpack2(acc3);
        o += fmaxf(p0.x, 0.f) * sF[j + 0] + fmaxf(p0.y, 0.f) * sF[j + 1];
        o += fmaxf(p1.x, 0.f) * sF[j + 2] + fmaxf(p1.y, 0.f) * sF[j + 3];
        o += fmaxf(p2.x, 0.f) * sF[j + 4] + fmaxf(p2.y, 0.f) * sF[j + 5];
        o += fmaxf(p3.x, 0.f) * sF[j + 6] + fmaxf(p3.y, 0.f) * sF[j + 7];
    }
    out[n] = o + bfc[0];
}

// ---------------- launch ----------------
extern "C" void kernel_launch(void* const* d_in, const int* in_sizes, int n_in,
                              void* d_out, int out_size) {
    const float* x   = (const float*)d_in[0];
    const void*  ei  = d_in[1];
    const float* W1  = (const float*)d_in[2];
    const float* b1  = (const float*)d_in[3];
    const float* W2  = (const float*)d_in[4];
    const float* b2  = (const float*)d_in[5];
    const float* W3  = (const float*)d_in[6];
    const float* b3  = (const float*)d_in[7];
    const float* Wfc = (const float*)d_in[8];
    const float* bfc = (const float*)d_in[9];
    float* out = (float*)d_out;

    const int TB = 256;
    const int gN = (N_NODES + TB - 1) / TB;

    // one persistent kernel: zero + gemm1 + count + scan + fill
    k_build<<<BLD_GRID, BLD_T>>>(ei, x, W1);

    // layer 1 aggregation (16-wide, + b1 + relu, dinv gathered)
    k_agg16<<<(N_NODES * 4 + TB - 1) / TB, TB>>>(b1);

    // layer 2: fused aggregate(16) + GEMM 16->64 -> fp16 h2'
    k_aggemm2<<<(N_NODES * 4 + TB - 1) / TB, TB>>>(W2, b2);

    // layer 3: fp16 aggregate 64-wide, then fused GEMM 64->128 + relu + FC
    k_agg64h<<<(N_NODES * 16 + TB - 1) / TB, TB>>>();
    k_final<<<gN, TB>>>(W3, b3, Wfc, bfc, out);
}

// round 10
// speedup vs baseline: 1.0602x; 1.0602x over previous
#include <cuda_runtime.h>
#include <cuda_fp16.h>

// Problem constants (fixed by setup_inputs)
static constexpr int N_NODES = 100000;
static constexpr int N_EDGES = 1600000;
static constexpr int SCAN_B  = 512;
static constexpr int SCAN_NB = (N_NODES + SCAN_B - 1) / SCAN_B;  // 196

// ---------------- scratch (static __device__, allocation-free) ----------------
__device__ int   g_cnt[N_NODES];
__device__ int   g_row[N_NODES + 1];
__device__ int   g_blkagg[SCAN_NB];
__device__ volatile int g_blkflag[SCAN_NB];
__device__ int   g_col[N_EDGES];
__device__ unsigned long long g_ep[N_EDGES];   // packed s(17) | d(17) | pos
__device__ float g_dinv[N_NODES];
__device__ float g_t1[N_NODES * 16];           // dinv * (x @ W1)
__device__ float g_h1[N_NODES * 16];           // dinv * relu(...)  (pre-scaled)
__device__ unsigned int g_h2h[N_NODES * 32];   // fp16 half2 h2'
__device__ float g_a3[N_NODES * 64];
__device__ int   g_is64;

// ---------------- f32x2 packed-FMA helpers (sm_103a) ----------------
typedef unsigned long long ull;
__device__ __forceinline__ ull pack2(float v) {
    ull r; asm("mov.b64 %0, {%1, %1};" : "=l"(r) : "f"(v)); return r;
}
__device__ __forceinline__ void ffma2(ull& d, ull a, ull b) {
    asm("fma.rn.f32x2 %0, %1, %2, %0;" : "+l"(d) : "l"(a), "l"(b));
}
__device__ __forceinline__ float2 unpack2(ull v) {
    float2 r; asm("mov.b64 {%0, %1}, %2;" : "=f"(r.x), "=f"(r.y) : "l"(v)); return r;
}
__device__ __forceinline__ unsigned int hadd2u(unsigned int a, unsigned int b) {
    __half2 r = __hadd2(*(const __half2*)&a, *(const __half2*)&b);
    return *(const unsigned int*)&r;
}
__device__ __forceinline__ void acc_h2(float2& acc, unsigned int h) {
    float2 f = __half22float2(*(const __half2*)&h);
    acc.x += f.x; acc.y += f.y;
}

// ---------------- graph build ----------------
__global__ void k_init(const unsigned int* __restrict__ e) {
    int i = blockIdx.x * blockDim.x + threadIdx.x;
    if (i < N_NODES) g_cnt[i] = 0;
    if (i < SCAN_NB) g_blkflag[i] = 0;
    if (i == 0) {
        int is64 = 1;
        for (int k = 0; k < 64; k++) {
            if (e[2 * k + 1] != 0u) { is64 = 0; break; }
        }
        g_is64 = is64;
    }
}

// decode + degree count; atomic return value = within-row position; pack 8B
__global__ void k_count(const void* e) {
    int i = blockIdx.x * blockDim.x + threadIdx.x;
    if (i >= N_EDGES) return;
    int s, d;
    if (g_is64) {
        const long long* p = (const long long*)e;
        s = (int)p[i];
        d = (int)p[N_EDGES + i];
    } else {
        const int* p = (const int*)e;
        s = p[i];
        d = p[N_EDGES + i];
    }
    if ((unsigned)d >= (unsigned)N_NODES || (unsigned)s >= (unsigned)N_NODES) {
        g_ep[i] = ~0ull;
        return;
    }
    int pos = atomicAdd(&g_cnt[d], 1);
    g_ep[i] = (ull)(unsigned)s | ((ull)(unsigned)d << 17) | ((ull)(unsigned)pos << 34);
}

// single-kernel exclusive scan; all 196 blocks resident in wave 1 -> no deadlock
__global__ void __launch_bounds__(SCAN_B) k_scan() {
    __shared__ int s[SCAN_B];
    __shared__ int sPre;
    int bid = blockIdx.x;
    int i = bid * SCAN_B + threadIdx.x;
    int v = (i < N_NODES) ? g_cnt[i] : 0;
    if (i < N_NODES) g_dinv[i] = rsqrtf((float)(v + 1));
    s[threadIdx.x] = v;
    __syncthreads();
    for (int d = 1; d < SCAN_B; d <<= 1) {
        int t = (threadIdx.x >= d) ? s[threadIdx.x - d] : 0;
        __syncthreads();
        s[threadIdx.x] += t;
        __syncthreads();
    }
    if (threadIdx.x == SCAN_B - 1) {
        g_blkagg[bid] = s[SCAN_B - 1];
        __threadfence();
        g_blkflag[bid] = 1;
    }
    if (threadIdx.x == 0) sPre = 0;
    __syncthreads();
    int p = 0;
    for (int b = threadIdx.x; b < bid; b += SCAN_B) {
        while (g_blkflag[b] == 0) { }
        p += *((volatile int*)&g_blkagg[b]);
    }
    if (p) atomicAdd(&sPre, p);
    __syncthreads();
    if (i < N_NODES) g_row[i] = sPre + s[threadIdx.x] - v;
    if (bid == 0 && threadIdx.x == 0) g_row[N_NODES] = N_EDGES;
}

// atomic-free fill
__global__ void k_fill() {
    int i = blockIdx.x * blockDim.x + threadIdx.x;
    if (i >= N_EDGES) return;
    ull ep = g_ep[i];
    int d = (int)((ep >> 17) & 0x1FFFFull);
    if (d >= N_NODES) return;
    int s   = (int)(ep & 0x1FFFFull);
    int pos = (int)(ep >> 34);
    g_col[g_row[d] + pos] = s;
}

// ---------------- layer 1 GEMM: t1' = dinv ⊙ (x @ W1)  (f32x2) -----------------
__global__ void __launch_bounds__(256) k_gemm1(const float* __restrict__ x,
                                               const float* __restrict__ W1) {
    __shared__ __align__(16) float sW[128 * 16];
    for (int idx = threadIdx.x; idx < 128 * 16; idx += 256) sW[idx] = W1[idx];
    __syncthreads();
    int n = blockIdx.x * 256 + threadIdx.x;
    if (n >= N_NODES) return;
    const float4* xr = (const float4*)(x + (size_t)n * 128);
    ull acc[8];
#pragma unroll
    for (int q = 0; q < 8; q++) acc[q] = 0ull;
#pragma unroll 4
    for (int k4 = 0; k4 < 32; k4++) {
        float4 v = __ldg(&xr[k4]);
#pragma unroll
        for (int kk = 0; kk < 4; kk++) {
            float xv = (kk == 0) ? v.x : (kk == 1) ? v.y : (kk == 2) ? v.z : v.w;
            ull av = pack2(xv);
            const ulonglong2* wr = (const ulonglong2*)(sW + (4 * k4 + kk) * 16);
            ulonglong2 w01 = wr[0], w23 = wr[1], w45 = wr[2], w67 = wr[3];
            ffma2(acc[0], av, w01.x); ffma2(acc[1], av, w01.y);
            ffma2(acc[2], av, w23.x); ffma2(acc[3], av, w23.y);
            ffma2(acc[4], av, w45.x); ffma2(acc[5], av, w45.y);
            ffma2(acc[6], av, w67.x); ffma2(acc[7], av, w67.y);
        }
    }
    float di = g_dinv[n];
    float4* o = (float4*)(g_t1 + (size_t)n * 16);
#pragma unroll
    for (int q = 0; q < 4; q++) {
        float2 p0 = unpack2(acc[2 * q]), p1 = unpack2(acc[2 * q + 1]);
        o[q] = make_float4(di * p0.x, di * p0.y, di * p1.x, di * p1.y);
    }
}

// ---------------- agg 16-wide (+b1+relu): h1' = relu(di²·S + di·b1) ------------
__global__ void __launch_bounds__(256) k_agg16(const float* __restrict__ bias) {
    const float4* __restrict__ t4 = (const float4*)g_t1;
    float4* __restrict__ o4 = (float4*)g_h1;
    int g = threadIdx.x & 3;
    int i = blockIdx.x * 64 + (threadIdx.x >> 2);
    if (i >= N_NODES) return;

    float4 acc = t4[(size_t)i * 4 + g];  // self loop
    int beg = g_row[i], end = g_row[i + 1];
    int j = beg;
    for (; j + 3 < end; j += 4) {
        int s0 = __ldg(&g_col[j]);
        int s1 = __ldg(&g_col[j + 1]);
        int s2 = __ldg(&g_col[j + 2]);
        int s3 = __ldg(&g_col[j + 3]);
        float4 v0 = __ldg(&t4[(size_t)s0 * 4 + g]);
        float4 v1 = __ldg(&t4[(size_t)s1 * 4 + g]);
        float4 v2 = __ldg(&t4[(size_t)s2 * 4 + g]);
        float4 v3 = __ldg(&t4[(size_t)s3 * 4 + g]);
        acc.x += (v0.x + v1.x) + (v2.x + v3.x);
        acc.y += (v0.y + v1.y) + (v2.y + v3.y);
        acc.z += (v0.z + v1.z) + (v2.z + v3.z);
        acc.w += (v0.w + v1.w) + (v2.w + v3.w);
    }
    for (; j < end; j++) {
        int s = __ldg(&g_col[j]);
        float4 v = __ldg(&t4[(size_t)s * 4 + g]);
        acc.x += v.x; acc.y += v.y; acc.z += v.z; acc.w += v.w;
    }
    float di = g_dinv[i];
    float4 b = ((const float4*)bias)[g];
    float d2 = di * di;
    float4 r;
    r.x = fmaxf(fmaf(d2, acc.x, di * b.x), 0.f);
    r.y = fmaxf(fmaf(d2, acc.y, di * b.y), 0.f);
    r.z = fmaxf(fmaf(d2, acc.z, di * b.z), 0.f);
    r.w = fmaxf(fmaf(d2, acc.w, di * b.w), 0.f);
    o4[(size_t)i * 4 + g] = r;
}

// ---------------- fused: agg(h1') 16-wide -> GEMM 16->64 -> fp16 h2' -----------
__global__ void __launch_bounds__(256) k_aggemm2(const float* __restrict__ W2,
                                                 const float* __restrict__ b2) {
    __shared__ __align__(16) float sW[16 * 64];
    __shared__ __align__(16) float sB[64];
    for (int idx = threadIdx.x; idx < 16 * 64; idx += 256) sW[idx] = W2[idx];
    if (threadIdx.x < 64) sB[threadIdx.x] = b2[threadIdx.x];
    __syncthreads();

    const float4* __restrict__ t4 = (const float4*)g_h1;
    int g = threadIdx.x & 3;
    int i = blockIdx.x * 64 + (threadIdx.x >> 2);
    if (i >= N_NODES) return;

    float4 acc = t4[(size_t)i * 4 + g];
    int beg = g_row[i], end = g_row[i + 1];
    int j = beg;
    for (; j + 3 < end; j += 4) {
        int s0 = __ldg(&g_col[j]);
        int s1 = __ldg(&g_col[j + 1]);
        int s2 = __ldg(&g_col[j + 2]);
        int s3 = __ldg(&g_col[j + 3]);
        float4 v0 = __ldg(&t4[(size_t)s0 * 4 + g]);
        float4 v1 = __ldg(&t4[(size_t)s1 * 4 + g]);
        float4 v2 = __ldg(&t4[(size_t)s2 * 4 + g]);
        float4 v3 = __ldg(&t4[(size_t)s3 * 4 + g]);
        acc.x += (v0.x + v1.x) + (v2.x + v3.x);
        acc.y += (v0.y + v1.y) + (v2.y + v3.y);
        acc.z += (v0.z + v1.z) + (v2.z + v3.z);
        acc.w += (v0.w + v1.w) + (v2.w + v3.w);
    }
    for (; j < end; j++) {
        int s = __ldg(&g_col[j]);
        float4 v = __ldg(&t4[(size_t)s * 4 + g]);
        acc.x += v.x; acc.y += v.y; acc.z += v.z; acc.w += v.w;
    }
    float di = g_dinv[i];
    float4 mya = make_float4(di * acc.x, di * acc.y, di * acc.z, di * acc.w);

    float a[16];
    int base = threadIdx.x & 31 & ~3;
#pragma unroll
    for (int q = 0; q < 4; q++) {
        int src = base + q;
        a[4 * q + 0] = __shfl_sync(0xffffffffu, mya.x, src);
        a[4 * q + 1] = __shfl_sync(0xffffffffu, mya.y, src);
        a[4 * q + 2] = __shfl_sync(0xffffffffu, mya.z, src);
        a[4 * q + 3] = __shfl_sync(0xffffffffu, mya.w, src);
    }

    ull oacc[8];
    const ull* sBu = (const ull*)sB;
#pragma unroll
    for (int m = 0; m < 8; m++) oacc[m] = sBu[g * 8 + m];
#pragma unroll
    for (int k = 0; k < 16; k++) {
        ull av = pack2(a[k]);
        const ull* wr = (const ull*)(sW + k * 64) + g * 8;
#pragma unroll
        for (int m = 0; m < 8; m++) ffma2(oacc[m], av, wr[m]);
    }
    unsigned int hs[8];
#pragma unroll
    for (int m = 0; m < 8; m++) {
        float2 pv = unpack2(oacc[m]);
        __half2 h = __floats2half2_rn(fmaxf(di * pv.x, 0.f), fmaxf(di * pv.y, 0.f));
        hs[m] = *(const unsigned int*)&h;
    }
    uint4* o = (uint4*)(g_h2h + (size_t)i * 32 + g * 8);
    o[0] = make_uint4(hs[0], hs[1], hs[2], hs[3]);
    o[1] = make_uint4(hs[4], hs[5], hs[6], hs[7]);
}

// ---------------- fp16 aggregation (64-wide), issue-optimized ------------------
// 8 threads/node, uint4 (8 halves) per thread. Edge PAIRS pre-reduced with
// HADD2 (one fp16 add), then converted once -> ~40% fewer issue slots.
__global__ void __launch_bounds__(256) k_agg64h() {
    const uint4* __restrict__ t = (const uint4*)g_h2h;  // 8 uint4 per node
    int g = threadIdx.x & 7;
    int i = blockIdx.x * 32 + (threadIdx.x >> 3);
    if (i >= N_NODES) return;

    float2 a0 = make_float2(0.f, 0.f), a1 = a0, a2 = a0, a3 = a0;
    {
        uint4 sv = __ldg(&t[(size_t)i * 8 + g]);   // self loop
        acc_h2(a0, sv.x); acc_h2(a1, sv.y); acc_h2(a2, sv.z); acc_h2(a3, sv.w);
    }
    int beg = g_row[i], end = g_row[i + 1];
    int j = beg;
    for (; j + 3 < end; j += 4) {
        int s0 = __ldg(&g_col[j]);
        int s1 = __ldg(&g_col[j + 1]);
        int s2 = __ldg(&g_col[j + 2]);
        int s3 = __ldg(&g_col[j + 3]);
        uint4 v0 = __ldg(&t[(size_t)s0 * 8 + g]);
        uint4 v1 = __ldg(&t[(size_t)s1 * 8 + g]);
        uint4 v2 = __ldg(&t[(size_t)s2 * 8 + g]);
        uint4 v3 = __ldg(&t[(size_t)s3 * 8 + g]);
        // pair-reduce in fp16 (one rounding per pair), convert once
        acc_h2(a0, hadd2u(v0.x, v1.x)); acc_h2(a0, hadd2u(v2.x, v3.x));
        acc_h2(a1, hadd2u(v0.y, v1.y)); acc_h2(a1, hadd2u(v2.y, v3.y));
        acc_h2(a2, hadd2u(v0.z, v1.z)); acc_h2(a2, hadd2u(v2.z, v3.z));
        acc_h2(a3, hadd2u(v0.w, v1.w)); acc_h2(a3, hadd2u(v2.w, v3.w));
    }
    if (j + 1 < end) {
        int s0 = __ldg(&g_col[j]);
        int s1 = __ldg(&g_col[j + 1]);
        uint4 v0 = __ldg(&t[(size_t)s0 * 8 + g]);
        uint4 v1 = __ldg(&t[(size_t)s1 * 8 + g]);
        acc_h2(a0, hadd2u(v0.x, v1.x));
        acc_h2(a1, hadd2u(v0.y, v1.y));
        acc_h2(a2, hadd2u(v0.z, v1.z));
        acc_h2(a3, hadd2u(v0.w, v1.w));
        j += 2;
    }
    if (j < end) {
        int s = __ldg(&g_col[j]);
        uint4 v = __ldg(&t[(size_t)s * 8 + g]);
        acc_h2(a0, v.x); acc_h2(a1, v.y); acc_h2(a2, v.z); acc_h2(a3, v.w);
    }
    float di = g_dinv[i];
    float4* o = (float4*)(g_a3 + (size_t)i * 64 + g * 8);
    o[0] = make_float4(di * a0.x, di * a0.y, di * a1.x, di * a1.y);
    o[1] = make_float4(di * a2.x, di * a2.y, di * a3.x, di * a3.y);
}

// ---------------- fused layer 3 + FC (f32x2) -----------------------------------
__global__ void __launch_bounds__(256) k_final(const float* __restrict__ W3,
                                               const float* __restrict__ b3,
                                               const float* __restrict__ Wfc,
                                               const float* __restrict__ bfc,
                                               float* __restrict__ out) {
    __shared__ __align__(16) float sW[64 * 128];
    __shared__ __align__(16) float sB[128];
    __shared__ __align__(16) float sF[128];
    for (int idx = threadIdx.x; idx < 64 * 128; idx += 256) sW[idx] = W3[idx];
    if (threadIdx.x < 128) {
        sB[threadIdx.x] = b3[threadIdx.x];
        sF[threadIdx.x] = Wfc[threadIdx.x];
    }
    __syncthreads();
    int n = blockIdx.x * 256 + threadIdx.x;
    if (n >= N_NODES) return;

    float a[64];
    const float4* ar = (const float4*)(g_a3 + (size_t)n * 64);
#pragma unroll
    for (int k4 = 0; k4 < 16; k4++) {
        float4 v = __ldg(&ar[k4]);
        a[4 * k4 + 0] = v.x; a[4 * k4 + 1] = v.y;
        a[4 * k4 + 2] = v.z; a[4 * k4 + 3] = v.w;
    }

    float o = 0.f;
#pragma unroll 1
    for (int j = 0; j < 128; j += 8) {
        const ulonglong2* bi = (const ulonglong2*)(sB + j);
        ulonglong2 b01 = bi[0], b23 = bi[1];
        ull acc0 = b01.x, acc1 = b01.y, acc2 = b23.x, acc3 = b23.y;
#pragma unroll
        for (int k = 0; k < 64; k++) {
            ull av = pack2(a[k]);
            const ulonglong2* w = (const ulonglong2*)(sW + k * 128 + j);
            ulonglong2 w01 = w[0], w23 = w[1];
            ffma2(acc0, av, w01.x);
            ffma2(acc1, av, w01.y);
            ffma2(acc2, av, w23.x);
            ffma2(acc3, av, w23.y);
        }
        float2 p0 = unpack2(acc0), p1 = unpack2(acc1);
        float2 p2 = unpack2(acc2), p3 = unpack2(acc3);
        o += fmaxf(p0.x, 0.f) * sF[j + 0] + fmaxf(p0.y, 0.f) * sF[j + 1];
        o += fmaxf(p1.x, 0.f) * sF[j + 2] + fmaxf(p1.y, 0.f) * sF[j + 3];
        o += fmaxf(p2.x, 0.f) * sF[j + 4] + fmaxf(p2.y, 0.f) * sF[j + 5];
        o += fmaxf(p3.x, 0.f) * sF[j + 6] + fmaxf(p3.y, 0.f) * sF[j + 7];
    }
    out[n] = o + bfc[0];
}

// ---------------- launch ----------------
extern "C" void kernel_launch(void* const* d_in, const int* in_sizes, int n_in,
                              void* d_out, int out_size) {
    const float* x   = (const float*)d_in[0];
    const void*  ei  = d_in[1];
    const float* W1  = (const float*)d_in[2];
    const float* b1  = (const float*)d_in[3];
    const float* W2  = (const float*)d_in[4];
    const float* b2  = (const float*)d_in[5];
    const float* W3  = (const float*)d_in[6];
    const float* b3  = (const float*)d_in[7];
    const float* Wfc = (const float*)d_in[8];
    const float* bfc = (const float*)d_in[9];
    float* out = (float*)d_out;

    const int TB = 256;
    const int gN = (N_NODES + TB - 1) / TB;
    const int gE = (N_EDGES + TB - 1) / TB;

    // graph construction: count(+pos packed) -> one-kernel scan -> atomic-free fill
    k_init<<<gN, TB>>>((const unsigned int*)ei);
    k_count<<<gE, TB>>>(ei);
    k_scan<<<SCAN_NB, SCAN_B>>>();
    k_fill<<<gE, TB>>>();

    // layer 1: GEMM (128->16, pre-scaled) then aggregate 16-wide (+b1+relu)
    k_gemm1<<<gN, TB>>>(x, W1);
    k_agg16<<<(N_NODES * 4 + TB - 1) / TB, TB>>>(b1);

    // layer 2: fused aggregate(16) + GEMM 16->64 -> fp16 h2'
    k_aggemm2<<<(N_NODES * 4 + TB - 1) / TB, TB>>>(W2, b2);

    // layer 3: fp16 aggregate 64-wide (issue-optimized), then fused GEMM + FC
    k_agg64h<<<(N_NODES * 8 + TB - 1) / TB, TB>>>();
    k_final<<<gN, TB>>>(W3, b3, Wfc, bfc, out);
}

// round 11
// speedup vs baseline: 1.0841x; 1.0225x over previous
#include <cuda_runtime.h>
#include <cuda_fp16.h>

// Problem constants (fixed by setup_inputs)
static constexpr int N_NODES = 100000;
static constexpr int N_EDGES = 1600000;
static constexpr int SCAN_B  = 512;
static constexpr int SCAN_NB = (N_NODES + SCAN_B - 1) / SCAN_B;  // 196
static constexpr int GE = N_EDGES / 256;          // 6250 (exact)
static constexpr int GN = (N_NODES + 255) / 256;  // 391

// ---------------- scratch (static __device__, zero-initialized) ----------------
__device__ int   g_cnt[N_NODES];               // zeroed by k_scan for next launch
__device__ int   g_row[N_NODES + 1];
__device__ int   g_blkagg[SCAN_NB];
__device__ volatile int g_blkflag[SCAN_NB];    // zeroed by k_count each launch
__device__ int   g_col[N_EDGES];
__device__ unsigned long long g_ep[N_EDGES];   // packed s(17) | d(17) | pos
__device__ float g_dinv[N_NODES];
__device__ unsigned int g_t1h[N_NODES * 8];    // fp16: dinv * (x @ W1)
__device__ unsigned int g_h1h[N_NODES * 8];    // fp16: dinv * relu(...)
__device__ unsigned int g_h2h[N_NODES * 32];   // fp16: dinv * relu(a2@W2+b2)
__device__ float g_a3[N_NODES * 64];

// ---------------- helpers ----------------
typedef unsigned long long ull;
__device__ __forceinline__ ull pack2(float v) {
    ull r; asm("mov.b64 %0, {%1, %1};" : "=l"(r) : "f"(v)); return r;
}
__device__ __forceinline__ void ffma2(ull& d, ull a, ull b) {
    asm("fma.rn.f32x2 %0, %1, %2, %0;" : "+l"(d) : "l"(a), "l"(b));
}
__device__ __forceinline__ float2 unpack2(ull v) {
    float2 r; asm("mov.b64 {%0, %1}, %2;" : "=f"(r.x), "=f"(r.y) : "l"(v)); return r;
}
__device__ __forceinline__ unsigned int hadd2u(unsigned int a, unsigned int b) {
    __half2 r = __hadd2(*(const __half2*)&a, *(const __half2*)&b);
    return *(const unsigned int*)&r;
}
__device__ __forceinline__ void acc_h2(float2& acc, unsigned int h) {
    float2 f = __half22float2(*(const __half2*)&h);
    acc.x += f.x; acc.y += f.y;
}
__device__ __forceinline__ unsigned int f2h2(float a, float b) {
    __half2 h = __floats2half2_rn(a, b);
    return *(const unsigned int*)&h;
}

// ---------------- k_count: detect + decode + degree count + pack ---------------
// (g_cnt arrives zeroed: statics zero-init on first run; k_scan re-zeroes after)
__global__ void __launch_bounds__(256) k_count(const void* e) {
    __shared__ int s_is64;
    int gtid = blockIdx.x * 256 + threadIdx.x;
    if (gtid < SCAN_NB) g_blkflag[gtid] = 0;   // reset for k_scan (runs after)
    if (threadIdx.x == 0) {
        const unsigned int* eu = (const unsigned int*)e;
        int is64 = 1;
#pragma unroll
        for (int k = 0; k < 16; k++)
            if (eu[2 * k + 1] != 0u) is64 = 0;
        s_is64 = is64;
    }
    __syncthreads();
    int i = gtid;
    if (i >= N_EDGES) return;
    int s, d;
    if (s_is64) {
        const long long* p = (const long long*)e;
        s = (int)p[i];
        d = (int)p[N_EDGES + i];
    } else {
        const int* p = (const int*)e;
        s = p[i];
        d = p[N_EDGES + i];
    }
    if ((unsigned)d >= (unsigned)N_NODES || (unsigned)s >= (unsigned)N_NODES) {
        g_ep[i] = ~0ull;
        return;
    }
    int pos = atomicAdd(&g_cnt[d], 1);
    g_ep[i] = (ull)(unsigned)s | ((ull)(unsigned)d << 17) | ((ull)(unsigned)pos << 34);
}

// ---------------- k_scan: exclusive scan + dinv + cnt re-zero ------------------
// all 196 blocks resident in wave 1 -> publish/spin cannot deadlock
__global__ void __launch_bounds__(SCAN_B) k_scan() {
    __shared__ int s[SCAN_B];
    __shared__ int sPre;
    int bid = blockIdx.x;
    int i = bid * SCAN_B + threadIdx.x;
    int v = (i < N_NODES) ? g_cnt[i] : 0;
    if (i < N_NODES) {
        g_dinv[i] = rsqrtf((float)(v + 1));
        g_cnt[i] = 0;                      // restore invariant for next launch
    }
    s[threadIdx.x] = v;
    __syncthreads();
    for (int d = 1; d < SCAN_B; d <<= 1) {
        int t = (threadIdx.x >= d) ? s[threadIdx.x - d] : 0;
        __syncthreads();
        s[threadIdx.x] += t;
        __syncthreads();
    }
    if (threadIdx.x == SCAN_B - 1) {
        g_blkagg[bid] = s[SCAN_B - 1];
        __threadfence();
        g_blkflag[bid] = 1;
    }
    if (threadIdx.x == 0) sPre = 0;
    __syncthreads();
    int p = 0;
    for (int b = threadIdx.x; b < bid; b += SCAN_B) {
        while (g_blkflag[b] == 0) { }
        p += *((volatile int*)&g_blkagg[b]);
    }
    if (p) atomicAdd(&sPre, p);
    __syncthreads();
    if (i < N_NODES) g_row[i] = sPre + s[threadIdx.x] - v;
    if (bid == 0 && threadIdx.x == 0) g_row[N_NODES] = N_EDGES;
}

// ---------------- merged: CSR fill (blocks < GE) + gemm1 (blocks >= GE) --------
// independent work after k_scan; mixes L2-scatter-bound and FMA-bound blocks
__global__ void __launch_bounds__(256) k_fillgemm1(const float* __restrict__ x,
                                                   const float* __restrict__ W1) {
    __shared__ __align__(16) float sW[128 * 16];
    if (blockIdx.x < GE) {
        int i = blockIdx.x * 256 + threadIdx.x;   // GE*256 == N_EDGES exactly
        ull ep = g_ep[i];
        int d = (int)((ep >> 17) & 0x1FFFFull);
        if (d < N_NODES)
            g_col[g_row[d] + (int)(ep >> 34)] = (int)(ep & 0x1FFFFull);
        return;
    }
    // ---- gemm1: t1' = fp16( dinv * (x @ W1) )
    for (int idx = threadIdx.x; idx < 128 * 16; idx += 256) sW[idx] = W1[idx];
    __syncthreads();
    int n = (blockIdx.x - GE) * 256 + threadIdx.x;
    if (n >= N_NODES) return;
    const float4* xr = (const float4*)(x + (size_t)n * 128);
    ull acc[8];
#pragma unroll
    for (int q = 0; q < 8; q++) acc[q] = 0ull;
#pragma unroll 4
    for (int k4 = 0; k4 < 32; k4++) {
        float4 v = __ldg(&xr[k4]);
#pragma unroll
        for (int kk = 0; kk < 4; kk++) {
            float xv = (kk == 0) ? v.x : (kk == 1) ? v.y : (kk == 2) ? v.z : v.w;
            ull av = pack2(xv);
            const ulonglong2* wr = (const ulonglong2*)(sW + (4 * k4 + kk) * 16);
            ulonglong2 w01 = wr[0], w23 = wr[1], w45 = wr[2], w67 = wr[3];
            ffma2(acc[0], av, w01.x); ffma2(acc[1], av, w01.y);
            ffma2(acc[2], av, w23.x); ffma2(acc[3], av, w23.y);
            ffma2(acc[4], av, w45.x); ffma2(acc[5], av, w45.y);
            ffma2(acc[6], av, w67.x); ffma2(acc[7], av, w67.y);
        }
    }
    float di = g_dinv[n];
    unsigned int hs[8];
#pragma unroll
    for (int q = 0; q < 8; q++) {
        float2 pv = unpack2(acc[q]);
        hs[q] = f2h2(di * pv.x, di * pv.y);
    }
    uint4* o = (uint4*)(g_t1h + (size_t)n * 8);
    o[0] = make_uint4(hs[0], hs[1], hs[2], hs[3]);
    o[1] = make_uint4(hs[4], hs[5], hs[6], hs[7]);
}

// ---------------- agg 16-wide fp16 (+b1+relu): h1' = relu(di²·S + di·b1) -------
// 2 threads/node, uint4 (8 halves) each, HADD2 pair-reduce
__global__ void __launch_bounds__(256) k_agg16h(const float* __restrict__ bias) {
    const uint4* __restrict__ t = (const uint4*)g_t1h;  // 2 uint4 per node
    int g = threadIdx.x & 1;
    int i = blockIdx.x * 128 + (threadIdx.x >> 1);
    if (i >= N_NODES) return;

    float2 a0 = make_float2(0.f, 0.f), a1 = a0, a2 = a0, a3 = a0;
    {
        uint4 sv = __ldg(&t[(size_t)i * 2 + g]);   // self loop
        acc_h2(a0, sv.x); acc_h2(a1, sv.y); acc_h2(a2, sv.z); acc_h2(a3, sv.w);
    }
    int beg = g_row[i], end = g_row[i + 1];
    int j = beg;
    for (; j + 3 < end; j += 4) {
        int s0 = __ldg(&g_col[j]);
        int s1 = __ldg(&g_col[j + 1]);
        int s2 = __ldg(&g_col[j + 2]);
        int s3 = __ldg(&g_col[j + 3]);
        uint4 v0 = __ldg(&t[(size_t)s0 * 2 + g]);
        uint4 v1 = __ldg(&t[(size_t)s1 * 2 + g]);
        uint4 v2 = __ldg(&t[(size_t)s2 * 2 + g]);
        uint4 v3 = __ldg(&t[(size_t)s3 * 2 + g]);
        acc_h2(a0, hadd2u(v0.x, v1.x)); acc_h2(a0, hadd2u(v2.x, v3.x));
        acc_h2(a1, hadd2u(v0.y, v1.y)); acc_h2(a1, hadd2u(v2.y, v3.y));
        acc_h2(a2, hadd2u(v0.z, v1.z)); acc_h2(a2, hadd2u(v2.z, v3.z));
        acc_h2(a3, hadd2u(v0.w, v1.w)); acc_h2(a3, hadd2u(v2.w, v3.w));
    }
    if (j + 1 < end) {
        int s0 = __ldg(&g_col[j]);
        int s1 = __ldg(&g_col[j + 1]);
        uint4 v0 = __ldg(&t[(size_t)s0 * 2 + g]);
        uint4 v1 = __ldg(&t[(size_t)s1 * 2 + g]);
        acc_h2(a0, hadd2u(v0.x, v1.x));
        acc_h2(a1, hadd2u(v0.y, v1.y));
        acc_h2(a2, hadd2u(v0.z, v1.z));
        acc_h2(a3, hadd2u(v0.w, v1.w));
        j += 2;
    }
    if (j < end) {
        int s = __ldg(&g_col[j]);
        uint4 v = __ldg(&t[(size_t)s * 2 + g]);
        acc_h2(a0, v.x); acc_h2(a1, v.y); acc_h2(a2, v.z); acc_h2(a3, v.w);
    }
    float di = g_dinv[i];
    float d2 = di * di;
    const float2* b2 = (const float2*)bias;   // features 8g..8g+7
    float2 bv0 = b2[4 * g + 0], bv1 = b2[4 * g + 1];
    float2 bv2 = b2[4 * g + 2], bv3 = b2[4 * g + 3];
    unsigned int h0 = f2h2(fmaxf(fmaf(d2, a0.x, di * bv0.x), 0.f),
                           fmaxf(fmaf(d2, a0.y, di * bv0.y), 0.f));
    unsigned int h1 = f2h2(fmaxf(fmaf(d2, a1.x, di * bv1.x), 0.f),
                           fmaxf(fmaf(d2, a1.y, di * bv1.y), 0.f));
    unsigned int h2 = f2h2(fmaxf(fmaf(d2, a2.x, di * bv2.x), 0.f),
                           fmaxf(fmaf(d2, a2.y, di * bv2.y), 0.f));
    unsigned int h3 = f2h2(fmaxf(fmaf(d2, a3.x, di * bv3.x), 0.f),
                           fmaxf(fmaf(d2, a3.y, di * bv3.y), 0.f));
    ((uint4*)(g_h1h + (size_t)i * 8))[g] = make_uint4(h0, h1, h2, h3);
}

// ---------------- fused: agg(h1',16) -> GEMM 16->64 -> fp16 h2' ----------------
// Phase 1: 2 threads/node aggregate fp16 rows -> fp32 a2 staged in smem.
// Phase 2: thread-per-node GEMM, weights via warp-uniform LDS broadcast.
__global__ void __launch_bounds__(256) k_aggemm2(const float* __restrict__ W2,
                                                 const float* __restrict__ b2) {
    __shared__ float sA[256][17];             // stride 17 -> conflict-free
    __shared__ __align__(16) float sW[16 * 64];
    __shared__ __align__(16) float sB[64];
    for (int idx = threadIdx.x; idx < 16 * 64; idx += 256) sW[idx] = W2[idx];
    if (threadIdx.x < 64) sB[threadIdx.x] = b2[threadIdx.x];
    __syncthreads();

    const uint4* __restrict__ t = (const uint4*)g_h1h;
    int nodeBase = blockIdx.x * 256;
    int g = threadIdx.x & 1;
#pragma unroll 1
    for (int pass = 0; pass < 2; pass++) {
        int local = pass * 128 + (threadIdx.x >> 1);
        int i = nodeBase + local;
        if (i < N_NODES) {
            float2 a0 = make_float2(0.f, 0.f), a1 = a0, a2 = a0, a3 = a0;
            {
                uint4 sv = __ldg(&t[(size_t)i * 2 + g]);
                acc_h2(a0, sv.x); acc_h2(a1, sv.y); acc_h2(a2, sv.z); acc_h2(a3, sv.w);
            }
            int beg = g_row[i], end = g_row[i + 1];
            int j = beg;
            for (; j + 3 < end; j += 4) {
                int s0 = __ldg(&g_col[j]);
                int s1 = __ldg(&g_col[j + 1]);
                int s2 = __ldg(&g_col[j + 2]);
                int s3 = __ldg(&g_col[j + 3]);
                uint4 v0 = __ldg(&t[(size_t)s0 * 2 + g]);
                uint4 v1 = __ldg(&t[(size_t)s1 * 2 + g]);
                uint4 v2 = __ldg(&t[(size_t)s2 * 2 + g]);
                uint4 v3 = __ldg(&t[(size_t)s3 * 2 + g]);
                acc_h2(a0, hadd2u(v0.x, v1.x)); acc_h2(a0, hadd2u(v2.x, v3.x));
                acc_h2(a1, hadd2u(v0.y, v1.y)); acc_h2(a1, hadd2u(v2.y, v3.y));
                acc_h2(a2, hadd2u(v0.z, v1.z)); acc_h2(a2, hadd2u(v2.z, v3.z));
                acc_h2(a3, hadd2u(v0.w, v1.w)); acc_h2(a3, hadd2u(v2.w, v3.w));
            }
            if (j + 1 < end) {
                int s0 = __ldg(&g_col[j]);
                int s1 = __ldg(&g_col[j + 1]);
                uint4 v0 = __ldg(&t[(size_t)s0 * 2 + g]);
                uint4 v1 = __ldg(&t[(size_t)s1 * 2 + g]);
                acc_h2(a0, hadd2u(v0.x, v1.x));
                acc_h2(a1, hadd2u(v0.y, v1.y));
                acc_h2(a2, hadd2u(v0.z, v1.z));
                acc_h2(a3, hadd2u(v0.w, v1.w));
                j += 2;
            }
            if (j < end) {
                int s = __ldg(&g_col[j]);
                uint4 v = __ldg(&t[(size_t)s * 2 + g]);
                acc_h2(a0, v.x); acc_h2(a1, v.y); acc_h2(a2, v.z); acc_h2(a3, v.w);
            }
            float di = g_dinv[i];
            float* row = &sA[local][g * 8];
            row[0] = di * a0.x; row[1] = di * a0.y;
            row[2] = di * a1.x; row[3] = di * a1.y;
            row[4] = di * a2.x; row[5] = di * a2.y;
            row[6] = di * a3.x; row[7] = di * a3.y;
        }
    }
    __syncthreads();

    // Phase 2: thread-per-node GEMM 16 -> 64
    int n = nodeBase + threadIdx.x;
    if (n >= N_NODES) return;
    float a[16];
#pragma unroll
    for (int k = 0; k < 16; k++) a[k] = sA[threadIdx.x][k];
    float di = g_dinv[n];

#pragma unroll
    for (int c = 0; c < 4; c++) {           // 16 outputs per chunk
        ull acc[8];
        const ull* sBu = (const ull*)sB;
#pragma unroll
        for (int m = 0; m < 8; m++) acc[m] = sBu[c * 8 + m];
#pragma unroll
        for (int k = 0; k < 16; k++) {
            ull av = pack2(a[k]);
            const ull* wr = (const ull*)(sW + k * 64) + c * 8;   // uniform -> broadcast
#pragma unroll
            for (int m = 0; m < 8; m++) ffma2(acc[m], av, wr[m]);
        }
        unsigned int hs[8];
#pragma unroll
        for (int m = 0; m < 8; m++) {
            float2 pv = unpack2(acc[m]);
            hs[m] = f2h2(fmaxf(di * pv.x, 0.f), fmaxf(di * pv.y, 0.f));
        }
        uint4* o = (uint4*)(g_h2h + (size_t)n * 32 + c * 8);
        o[0] = make_uint4(hs[0], hs[1], hs[2], hs[3]);
        o[1] = make_uint4(hs[4], hs[5], hs[6], hs[7]);
    }
}

// ---------------- fp16 aggregation (64-wide), issue-optimized ------------------
__global__ void __launch_bounds__(256) k_agg64h() {
    const uint4* __restrict__ t = (const uint4*)g_h2h;  // 8 uint4 per node
    int g = threadIdx.x & 7;
    int i = blockIdx.x * 32 + (threadIdx.x >> 3);
    if (i >= N_NODES) return;

    float2 a0 = make_float2(0.f, 0.f), a1 = a0, a2 = a0, a3 = a0;
    {
        uint4 sv = __ldg(&t[(size_t)i * 8 + g]);   // self loop
        acc_h2(a0, sv.x); acc_h2(a1, sv.y); acc_h2(a2, sv.z); acc_h2(a3, sv.w);
    }
    int beg = g_row[i], end = g_row[i + 1];
    int j = beg;
    for (; j + 3 < end; j += 4) {
        int s0 = __ldg(&g_col[j]);
        int s1 = __ldg(&g_col[j + 1]);
        int s2 = __ldg(&g_col[j + 2]);
        int s3 = __ldg(&g_col[j + 3]);
        uint4 v0 = __ldg(&t[(size_t)s0 * 8 + g]);
        uint4 v1 = __ldg(&t[(size_t)s1 * 8 + g]);
        uint4 v2 = __ldg(&t[(size_t)s2 * 8 + g]);
        uint4 v3 = __ldg(&t[(size_t)s3 * 8 + g]);
        acc_h2(a0, hadd2u(v0.x, v1.x)); acc_h2(a0, hadd2u(v2.x, v3.x));
        acc_h2(a1, hadd2u(v0.y, v1.y)); acc_h2(a1, hadd2u(v2.y, v3.y));
        acc_h2(a2, hadd2u(v0.z, v1.z)); acc_h2(a2, hadd2u(v2.z, v3.z));
        acc_h2(a3, hadd2u(v0.w, v1.w)); acc_h2(a3, hadd2u(v2.w, v3.w));
    }
    if (j + 1 < end) {
        int s0 = __ldg(&g_col[j]);
        int s1 = __ldg(&g_col[j + 1]);
        uint4 v0 = __ldg(&t[(size_t)s0 * 8 + g]);
        uint4 v1 = __ldg(&t[(size_t)s1 * 8 + g]);
        acc_h2(a0, hadd2u(v0.x, v1.x));
        acc_h2(a1, hadd2u(v0.y, v1.y));
        acc_h2(a2, hadd2u(v0.z, v1.z));
        acc_h2(a3, hadd2u(v0.w, v1.w));
        j += 2;
    }
    if (j < end) {
        int s = __ldg(&g_col[j]);
        uint4 v = __ldg(&t[(size_t)s * 8 + g]);
        acc_h2(a0, v.x); acc_h2(a1, v.y); acc_h2(a2, v.z); acc_h2(a3, v.w);
    }
    float di = g_dinv[i];
    float4* o = (float4*)(g_a3 + (size_t)i * 64 + g * 8);
    o[0] = make_float4(di * a0.x, di * a0.y, di * a1.x, di * a1.y);
    o[1] = make_float4(di * a2.x, di * a2.y, di * a3.x, di * a3.y);
}

// ---------------- fused layer 3 + FC (f32x2) -----------------------------------
__global__ void __launch_bounds__(256) k_final(const float* __restrict__ W3,
                                               const float* __restrict__ b3,
                                               const float* __restrict__ Wfc,
                                               const float* __restrict__ bfc,
                                               float* __restrict__ out) {
    __shared__ __align__(16) float sW[64 * 128];
    __shared__ __align__(16) float sB[128];
    __shared__ __align__(16) float sF[128];
    for (int idx = threadIdx.x; idx < 64 * 128; idx += 256) sW[idx] = W3[idx];
    if (threadIdx.x < 128) {
        sB[threadIdx.x] = b3[threadIdx.x];
        sF[threadIdx.x] = Wfc[threadIdx.x];
    }
    __syncthreads();
    int n = blockIdx.x * 256 + threadIdx.x;
    if (n >= N_NODES) return;

    float a[64];
    const float4* ar = (const float4*)(g_a3 + (size_t)n * 64);
#pragma unroll
    for (int k4 = 0; k4 < 16; k4++) {
        float4 v = __ldg(&ar[k4]);
        a[4 * k4 + 0] = v.x; a[4 * k4 + 1] = v.y;
        a[4 * k4 + 2] = v.z; a[4 * k4 + 3] = v.w;
    }

    float o = 0.f;
#pragma unroll 1
    for (int j = 0; j < 128; j += 8) {
        const ulonglong2* bi = (const ulonglong2*)(sB + j);
        ulonglong2 b01 = bi[0], b23 = bi[1];
        ull acc0 = b01.x, acc1 = b01.y, acc2 = b23.x, acc3 = b23.y;
#pragma unroll
        for (int k = 0; k < 64; k++) {
            ull av = pack2(a[k]);
            const ulonglong2* w = (const ulonglong2*)(sW + k * 128 + j);
            ulonglong2 w01 = w[0], w23 = w[1];
            ffma2(acc0, av, w01.x);
            ffma2(acc1, av, w01.y);
            ffma2(acc2, av, w23.x);
            ffma2(acc3, av, w23.y);
        }
        float2 p0 = unpack2(acc0), p1 = unpack2(acc1);
        float2 p2 = unpack2(acc2), p3 = unpack2(acc3);
        o += fmaxf(p0.x, 0.f) * sF[j + 0] + fmaxf(p0.y, 0.f) * sF[j + 1];
        o += fmaxf(p1.x, 0.f) * sF[j + 2] + fmaxf(p1.y, 0.f) * sF[j + 3];
        o += fmaxf(p2.x, 0.f) * sF[j + 4] + fmaxf(p2.y, 0.f) * sF[j + 5];
        o += fmaxf(p3.x, 0.f) * sF[j + 6] + fmaxf(p3.y, 0.f) * sF[j + 7];
    }
    out[n] = o + bfc[0];
}

// ---------------- launch ----------------
extern "C" void kernel_launch(void* const* d_in, const int* in_sizes, int n_in,
                              void* d_out, int out_size) {
    const float* x   = (const float*)d_in[0];
    const void*  ei  = d_in[1];
    const float* W1  = (const float*)d_in[2];
    const float* b1  = (const float*)d_in[3];
    const float* W2  = (const float*)d_in[4];
    const float* b2  = (const float*)d_in[5];
    const float* W3  = (const float*)d_in[6];
    const float* b3  = (const float*)d_in[7];
    const float* Wfc = (const float*)d_in[8];
    const float* bfc = (const float*)d_in[9];
    float* out = (float*)d_out;

    // graph build: count(+detect+flag reset) -> scan(+dinv+cnt reset)
    k_count<<<GE, 256>>>(ei);
    k_scan<<<SCAN_NB, SCAN_B>>>();

    // merged CSR fill + layer-1 GEMM (independent, both depend on scan)
    k_fillgemm1<<<GE + GN, 256>>>(x, W1);

    // layer 1 aggregation (fp16, 2 threads/node, +b1+relu)
    k_agg16h<<<(N_NODES + 127) / 128, 256>>>(b1);

    // layer 2: fused aggregate(16, fp16) + GEMM 16->64 -> fp16 h2'
    k_aggemm2<<<(N_NODES + 255) / 256, 256>>>(W2, b2);

    // layer 3: fp16 aggregate 64-wide, then fused GEMM 64->128 + relu + FC
    k_agg64h<<<(N_NODES + 31) / 32, 256>>>();
    k_final<<<(N_NODES + 255) / 256, 256>>>(W3, b3, Wfc, bfc, out);
}

// round 13
// speedup vs baseline: 1.4323x; 1.3211x over previous
#include <cuda_runtime.h>
#include <cuda_fp16.h>

// Problem constants (fixed by setup_inputs)
static constexpr int N_NODES = 100000;
static constexpr int N_EDGES = 1600000;
static constexpr int SCAN_B  = 512;
static constexpr int SCAN_NB = (N_NODES + SCAN_B - 1) / SCAN_B;  // 196
static constexpr int GE = N_EDGES / 256;          // 6250 (exact)
static constexpr int GN = (N_NODES + 255) / 256;  // 391

// ---------------- scratch (static __device__, zero-initialized) ----------------
__device__ int   g_cnt[N_NODES];               // zeroed by k_scan for next launch
__device__ int   g_row[N_NODES + 1];
__device__ int   g_blkagg[SCAN_NB];
__device__ volatile int g_blkflag[SCAN_NB];    // zeroed by k_count each launch
__device__ int   g_col[N_EDGES];
__device__ unsigned long long g_ep[N_EDGES];   // packed s(17) | d(17) | pos
__device__ float g_dinv[N_NODES];
__device__ unsigned int g_t1h[N_NODES * 8];    // fp16: dinv * (x @ W1)
__device__ unsigned int g_h1h[N_NODES * 8];    // fp16: dinv * relu(...)
__device__ unsigned int g_h2h[N_NODES * 32];   // fp16: dinv * relu(a2@W2+b2)
__device__ unsigned int g_a3h[N_NODES * 32];   // fp16: dinv * sum  (MMA A operand)

// ---------------- helpers ----------------
typedef unsigned long long ull;
__device__ __forceinline__ ull pack2(float v) {
    ull r; asm("mov.b64 %0, {%1, %1};" : "=l"(r) : "f"(v)); return r;
}
__device__ __forceinline__ void ffma2(ull& d, ull a, ull b) {
    asm("fma.rn.f32x2 %0, %1, %2, %0;" : "+l"(d) : "l"(a), "l"(b));
}
__device__ __forceinline__ float2 unpack2(ull v) {
    float2 r; asm("mov.b64 {%0, %1}, %2;" : "=f"(r.x), "=f"(r.y) : "l"(v)); return r;
}
__device__ __forceinline__ unsigned int hadd2u(unsigned int a, unsigned int b) {
    __half2 r = __hadd2(*(const __half2*)&a, *(const __half2*)&b);
    return *(const unsigned int*)&r;
}
__device__ __forceinline__ void acc_h2(float2& acc, unsigned int h) {
    float2 f = __half22float2(*(const __half2*)&h);
    acc.x += f.x; acc.y += f.y;
}
__device__ __forceinline__ unsigned int f2h2(float a, float b) {
    __half2 h = __floats2half2_rn(a, b);
    return *(const unsigned int*)&h;
}

// ---------------- k_count: detect + decode + degree count + pack ---------------
__global__ void __launch_bounds__(256) k_count(const void* e) {
    __shared__ int s_is64;
    int gtid = blockIdx.x * 256 + threadIdx.x;
    if (gtid < SCAN_NB) g_blkflag[gtid] = 0;   // reset for k_scan (runs after)
    if (threadIdx.x == 0) {
        const unsigned int* eu = (const unsigned int*)e;
        int is64 = 1;
#pragma unroll
        for (int k = 0; k < 16; k++)
            if (eu[2 * k + 1] != 0u) is64 = 0;
        s_is64 = is64;
    }
    __syncthreads();
    int i = gtid;
    if (i >= N_EDGES) return;
    int s, d;
    if (s_is64) {
        const long long* p = (const long long*)e;
        s = (int)p[i];
        d = (int)p[N_EDGES + i];
    } else {
        const int* p = (const int*)e;
        s = p[i];
        d = p[N_EDGES + i];
    }
    if ((unsigned)d >= (unsigned)N_NODES || (unsigned)s >= (unsigned)N_NODES) {
        g_ep[i] = ~0ull;
        return;
    }
    int pos = atomicAdd(&g_cnt[d], 1);
    g_ep[i] = (ull)(unsigned)s | ((ull)(unsigned)d << 17) | ((ull)(unsigned)pos << 34);
}

// ---------------- k_scan: exclusive scan + dinv + cnt re-zero ------------------
__global__ void __launch_bounds__(SCAN_B) k_scan() {
    __shared__ int s[SCAN_B];
    __shared__ int sPre;
    int bid = blockIdx.x;
    int i = bid * SCAN_B + threadIdx.x;
    int v = (i < N_NODES) ? g_cnt[i] : 0;
    if (i < N_NODES) {
        g_dinv[i] = rsqrtf((float)(v + 1));
        g_cnt[i] = 0;                      // restore invariant for next launch
    }
    s[threadIdx.x] = v;
    __syncthreads();
    for (int d = 1; d < SCAN_B; d <<= 1) {
        int t = (threadIdx.x >= d) ? s[threadIdx.x - d] : 0;
        __syncthreads();
        s[threadIdx.x] += t;
        __syncthreads();
    }
    if (threadIdx.x == SCAN_B - 1) {
        g_blkagg[bid] = s[SCAN_B - 1];
        __threadfence();
        g_blkflag[bid] = 1;
    }
    if (threadIdx.x == 0) sPre = 0;
    __syncthreads();
    int p = 0;
    for (int b = threadIdx.x; b < bid; b += SCAN_B) {
        while (g_blkflag[b] == 0) { }
        p += *((volatile int*)&g_blkagg[b]);
    }
    if (p) atomicAdd(&sPre, p);
    __syncthreads();
    if (i < N_NODES) g_row[i] = sPre + s[threadIdx.x] - v;
    if (bid == 0 && threadIdx.x == 0) g_row[N_NODES] = N_EDGES;
}

// ---------------- merged: CSR fill (blocks < GE) + gemm1 (blocks >= GE) --------
__global__ void __launch_bounds__(256) k_fillgemm1(const float* __restrict__ x,
                                                   const float* __restrict__ W1) {
    __shared__ __align__(16) float sW[128 * 16];
    if (blockIdx.x < GE) {
        int i = blockIdx.x * 256 + threadIdx.x;
        ull ep = g_ep[i];
        int d = (int)((ep >> 17) & 0x1FFFFull);
        if (d < N_NODES)
            g_col[g_row[d] + (int)(ep >> 34)] = (int)(ep & 0x1FFFFull);
        return;
    }
    for (int idx = threadIdx.x; idx < 128 * 16; idx += 256) sW[idx] = W1[idx];
    __syncthreads();
    int n = (blockIdx.x - GE) * 256 + threadIdx.x;
    if (n >= N_NODES) return;
    const float4* xr = (const float4*)(x + (size_t)n * 128);
    ull acc[8];
#pragma unroll
    for (int q = 0; q < 8; q++) acc[q] = 0ull;
#pragma unroll 4
    for (int k4 = 0; k4 < 32; k4++) {
        float4 v = __ldg(&xr[k4]);
#pragma unroll
        for (int kk = 0; kk < 4; kk++) {
            float xv = (kk == 0) ? v.x : (kk == 1) ? v.y : (kk == 2) ? v.z : v.w;
            ull av = pack2(xv);
            const ulonglong2* wr = (const ulonglong2*)(sW + (4 * k4 + kk) * 16);
            ulonglong2 w01 = wr[0], w23 = wr[1], w45 = wr[2], w67 = wr[3];
            ffma2(acc[0], av, w01.x); ffma2(acc[1], av, w01.y);
            ffma2(acc[2], av, w23.x); ffma2(acc[3], av, w23.y);
            ffma2(acc[4], av, w45.x); ffma2(acc[5], av, w45.y);
            ffma2(acc[6], av, w67.x); ffma2(acc[7], av, w67.y);
        }
    }
    float di = g_dinv[n];
    unsigned int hs[8];
#pragma unroll
    for (int q = 0; q < 8; q++) {
        float2 pv = unpack2(acc[q]);
        hs[q] = f2h2(di * pv.x, di * pv.y);
    }
    uint4* o = (uint4*)(g_t1h + (size_t)n * 8);
    o[0] = make_uint4(hs[0], hs[1], hs[2], hs[3]);
    o[1] = make_uint4(hs[4], hs[5], hs[6], hs[7]);
}

// ---------------- agg 16-wide fp16 (+b1+relu), 8-edge unroll for MLP -----------
__global__ void __launch_bounds__(256) k_agg16h(const float* __restrict__ bias) {
    const uint4* __restrict__ t = (const uint4*)g_t1h;  // 2 uint4 per node
    int g = threadIdx.x & 1;
    int i = blockIdx.x * 128 + (threadIdx.x >> 1);
    if (i >= N_NODES) return;

    float2 a0 = make_float2(0.f, 0.f), a1 = a0, a2 = a0, a3 = a0;
    {
        uint4 sv = __ldg(&t[(size_t)i * 2 + g]);   // self loop
        acc_h2(a0, sv.x); acc_h2(a1, sv.y); acc_h2(a2, sv.z); acc_h2(a3, sv.w);
    }
    int beg = g_row[i], end = g_row[i + 1];
    int j = beg;
    for (; j + 7 < end; j += 8) {
        int s0 = __ldg(&g_col[j]);
        int s1 = __ldg(&g_col[j + 1]);
        int s2 = __ldg(&g_col[j + 2]);
        int s3 = __ldg(&g_col[j + 3]);
        int s4 = __ldg(&g_col[j + 4]);
        int s5 = __ldg(&g_col[j + 5]);
        int s6 = __ldg(&g_col[j + 6]);
        int s7 = __ldg(&g_col[j + 7]);
        uint4 v0 = __ldg(&t[(size_t)s0 * 2 + g]);
        uint4 v1 = __ldg(&t[(size_t)s1 * 2 + g]);
        uint4 v2 = __ldg(&t[(size_t)s2 * 2 + g]);
        uint4 v3 = __ldg(&t[(size_t)s3 * 2 + g]);
        uint4 v4 = __ldg(&t[(size_t)s4 * 2 + g]);
        uint4 v5 = __ldg(&t[(size_t)s5 * 2 + g]);
        uint4 v6 = __ldg(&t[(size_t)s6 * 2 + g]);
        uint4 v7 = __ldg(&t[(size_t)s7 * 2 + g]);
        acc_h2(a0, hadd2u(v0.x, v1.x)); acc_h2(a0, hadd2u(v2.x, v3.x));
        acc_h2(a0, hadd2u(v4.x, v5.x)); acc_h2(a0, hadd2u(v6.x, v7.x));
        acc_h2(a1, hadd2u(v0.y, v1.y)); acc_h2(a1, hadd2u(v2.y, v3.y));
        acc_h2(a1, hadd2u(v4.y, v5.y)); acc_h2(a1, hadd2u(v6.y, v7.y));
        acc_h2(a2, hadd2u(v0.z, v1.z)); acc_h2(a2, hadd2u(v2.z, v3.z));
        acc_h2(a2, hadd2u(v4.z, v5.z)); acc_h2(a2, hadd2u(v6.z, v7.z));
        acc_h2(a3, hadd2u(v0.w, v1.w)); acc_h2(a3, hadd2u(v2.w, v3.w));
        acc_h2(a3, hadd2u(v4.w, v5.w)); acc_h2(a3, hadd2u(v6.w, v7.w));
    }
    for (; j + 1 < end; j += 2) {
        int s0 = __ldg(&g_col[j]);
        int s1 = __ldg(&g_col[j + 1]);
        uint4 v0 = __ldg(&t[(size_t)s0 * 2 + g]);
        uint4 v1 = __ldg(&t[(size_t)s1 * 2 + g]);
        acc_h2(a0, hadd2u(v0.x, v1.x));
        acc_h2(a1, hadd2u(v0.y, v1.y));
        acc_h2(a2, hadd2u(v0.z, v1.z));
        acc_h2(a3, hadd2u(v0.w, v1.w));
    }
    if (j < end) {
        int s = __ldg(&g_col[j]);
        uint4 v = __ldg(&t[(size_t)s * 2 + g]);
        acc_h2(a0, v.x); acc_h2(a1, v.y); acc_h2(a2, v.z); acc_h2(a3, v.w);
    }
    float di = g_dinv[i];
    float d2 = di * di;
    const float2* b2 = (const float2*)bias;
    float2 bv0 = b2[4 * g + 0], bv1 = b2[4 * g + 1];
    float2 bv2 = b2[4 * g + 2], bv3 = b2[4 * g + 3];
    unsigned int h0 = f2h2(fmaxf(fmaf(d2, a0.x, di * bv0.x), 0.f),
                           fmaxf(fmaf(d2, a0.y, di * bv0.y), 0.f));
    unsigned int h1 = f2h2(fmaxf(fmaf(d2, a1.x, di * bv1.x), 0.f),
                           fmaxf(fmaf(d2, a1.y, di * bv1.y), 0.f));
    unsigned int h2 = f2h2(fmaxf(fmaf(d2, a2.x, di * bv2.x), 0.f),
                           fmaxf(fmaf(d2, a2.y, di * bv2.y), 0.f));
    unsigned int h3 = f2h2(fmaxf(fmaf(d2, a3.x, di * bv3.x), 0.f),
                           fmaxf(fmaf(d2, a3.y, di * bv3.y), 0.f));
    ((uint4*)(g_h1h + (size_t)i * 8))[g] = make_uint4(h0, h1, h2, h3);
}

// ---------------- fused: agg(h1',16) -> GEMM 16->64 -> fp16 h2' ----------------
__global__ void __launch_bounds__(256) k_aggemm2(const float* __restrict__ W2,
                                                 const float* __restrict__ b2) {
    __shared__ float sA[256][17];
    __shared__ __align__(16) float sW[16 * 64];
    __shared__ __align__(16) float sB[64];
    for (int idx = threadIdx.x; idx < 16 * 64; idx += 256) sW[idx] = W2[idx];
    if (threadIdx.x < 64) sB[threadIdx.x] = b2[threadIdx.x];
    __syncthreads();

    const uint4* __restrict__ t = (const uint4*)g_h1h;
    int nodeBase = blockIdx.x * 256;
    int g = threadIdx.x & 1;
#pragma unroll 1
    for (int pass = 0; pass < 2; pass++) {
        int local = pass * 128 + (threadIdx.x >> 1);
        int i = nodeBase + local;
        if (i < N_NODES) {
            float2 a0 = make_float2(0.f, 0.f), a1 = a0, a2 = a0, a3 = a0;
            {
                uint4 sv = __ldg(&t[(size_t)i * 2 + g]);
                acc_h2(a0, sv.x); acc_h2(a1, sv.y); acc_h2(a2, sv.z); acc_h2(a3, sv.w);
            }
            int beg = g_row[i], end = g_row[i + 1];
            int j = beg;
            for (; j + 3 < end; j += 4) {
                int s0 = __ldg(&g_col[j]);
                int s1 = __ldg(&g_col[j + 1]);
                int s2 = __ldg(&g_col[j + 2]);
                int s3 = __ldg(&g_col[j + 3]);
                uint4 v0 = __ldg(&t[(size_t)s0 * 2 + g]);
                uint4 v1 = __ldg(&t[(size_t)s1 * 2 + g]);
                uint4 v2 = __ldg(&t[(size_t)s2 * 2 + g]);
                uint4 v3 = __ldg(&t[(size_t)s3 * 2 + g]);
                acc_h2(a0, hadd2u(v0.x, v1.x)); acc_h2(a0, hadd2u(v2.x, v3.x));
                acc_h2(a1, hadd2u(v0.y, v1.y)); acc_h2(a1, hadd2u(v2.y, v3.y));
                acc_h2(a2, hadd2u(v0.z, v1.z)); acc_h2(a2, hadd2u(v2.z, v3.z));
                acc_h2(a3, hadd2u(v0.w, v1.w)); acc_h2(a3, hadd2u(v2.w, v3.w));
            }
            if (j + 1 < end) {
                int s0 = __ldg(&g_col[j]);
                int s1 = __ldg(&g_col[j + 1]);
                uint4 v0 = __ldg(&t[(size_t)s0 * 2 + g]);
                uint4 v1 = __ldg(&t[(size_t)s1 * 2 + g]);
                acc_h2(a0, hadd2u(v0.x, v1.x));
                acc_h2(a1, hadd2u(v0.y, v1.y));
                acc_h2(a2, hadd2u(v0.z, v1.z));
                acc_h2(a3, hadd2u(v0.w, v1.w));
                j += 2;
            }
            if (j < end) {
                int s = __ldg(&g_col[j]);
                uint4 v = __ldg(&t[(size_t)s * 2 + g]);
                acc_h2(a0, v.x); acc_h2(a1, v.y); acc_h2(a2, v.z); acc_h2(a3, v.w);
            }
            float di = g_dinv[i];
            float* row = &sA[local][g * 8];
            row[0] = di * a0.x; row[1] = di * a0.y;
            row[2] = di * a1.x; row[3] = di * a1.y;
            row[4] = di * a2.x; row[5] = di * a2.y;
            row[6] = di * a3.x; row[7] = di * a3.y;
        }
    }
    __syncthreads();

    int n = nodeBase + threadIdx.x;
    if (n >= N_NODES) return;
    float a[16];
#pragma unroll
    for (int k = 0; k < 16; k++) a[k] = sA[threadIdx.x][k];
    float di = g_dinv[n];

#pragma unroll
    for (int c = 0; c < 4; c++) {
        ull acc[8];
        const ull* sBu = (const ull*)sB;
#pragma unroll
        for (int m = 0; m < 8; m++) acc[m] = sBu[c * 8 + m];
#pragma unroll
        for (int k = 0; k < 16; k++) {
            ull av = pack2(a[k]);
            const ull* wr = (const ull*)(sW + k * 64) + c * 8;
#pragma unroll
            for (int m = 0; m < 8; m++) ffma2(acc[m], av, wr[m]);
        }
        unsigned int hs[8];
#pragma unroll
        for (int m = 0; m < 8; m++) {
            float2 pv = unpack2(acc[m]);
            hs[m] = f2h2(fmaxf(di * pv.x, 0.f), fmaxf(di * pv.y, 0.f));
        }
        uint4* o = (uint4*)(g_h2h + (size_t)n * 32 + c * 8);
        o[0] = make_uint4(hs[0], hs[1], hs[2], hs[3]);
        o[1] = make_uint4(hs[4], hs[5], hs[6], hs[7]);
    }
}

// ---------------- fp16 aggregation (64-wide) -> fp16 a3 ------------------------
__global__ void __launch_bounds__(256) k_agg64h() {
    const uint4* __restrict__ t = (const uint4*)g_h2h;
    int g = threadIdx.x & 7;
    int i = blockIdx.x * 32 + (threadIdx.x >> 3);
    if (i >= N_NODES) return;

    float2 a0 = make_float2(0.f, 0.f), a1 = a0, a2 = a0, a3 = a0;
    {
        uint4 sv = __ldg(&t[(size_t)i * 8 + g]);
        acc_h2(a0, sv.x); acc_h2(a1, sv.y); acc_h2(a2, sv.z); acc_h2(a3, sv.w);
    }
    int beg = g_row[i], end = g_row[i + 1];
    int j = beg;
    for (; j + 3 < end; j += 4) {
        int s0 = __ldg(&g_col[j]);
        int s1 = __ldg(&g_col[j + 1]);
        int s2 = __ldg(&g_col[j + 2]);
        int s3 = __ldg(&g_col[j + 3]);
        uint4 v0 = __ldg(&t[(size_t)s0 * 8 + g]);
        uint4 v1 = __ldg(&t[(size_t)s1 * 8 + g]);
        uint4 v2 = __ldg(&t[(size_t)s2 * 8 + g]);
        uint4 v3 = __ldg(&t[(size_t)s3 * 8 + g]);
        acc_h2(a0, hadd2u(v0.x, v1.x)); acc_h2(a0, hadd2u(v2.x, v3.x));
        acc_h2(a1, hadd2u(v0.y, v1.y)); acc_h2(a1, hadd2u(v2.y, v3.y));
        acc_h2(a2, hadd2u(v0.z, v1.z)); acc_h2(a2, hadd2u(v2.z, v3.z));
        acc_h2(a3, hadd2u(v0.w, v1.w)); acc_h2(a3, hadd2u(v2.w, v3.w));
    }
    if (j + 1 < end) {
        int s0 = __ldg(&g_col[j]);
        int s1 = __ldg(&g_col[j + 1]);
        uint4 v0 = __ldg(&t[(size_t)s0 * 8 + g]);
        uint4 v1 = __ldg(&t[(size_t)s1 * 8 + g]);
        acc_h2(a0, hadd2u(v0.x, v1.x));
        acc_h2(a1, hadd2u(v0.y, v1.y));
        acc_h2(a2, hadd2u(v0.z, v1.z));
        acc_h2(a3, hadd2u(v0.w, v1.w));
        j += 2;
    }
    if (j < end) {
        int s = __ldg(&g_col[j]);
        uint4 v = __ldg(&t[(size_t)s * 8 + g]);
        acc_h2(a0, v.x); acc_h2(a1, v.y); acc_h2(a2, v.z); acc_h2(a3, v.w);
    }
    float di = g_dinv[i];
    ((uint4*)(g_a3h + (size_t)i * 32))[g] =
        make_uint4(f2h2(di * a0.x, di * a0.y), f2h2(di * a1.x, di * a1.y),
                   f2h2(di * a2.x, di * a2.y), f2h2(di * a3.x, di * a3.y));
}

// ---------------- layer 3 + FC on HMMA (mma.sync m16n8k16, sm_80+ baseline) ----
// Block: 256 threads = 8 warps; warp w owns nodes [blk*128 + 16w, +16).
// D(16x128) = A(16x64 fp16 a3) @ B(64x128 fp16 W3), f32 accum.
// out[n] = sum_j relu(D[n,j] + b3[j]) * Wfc[j] + bfc.
// B fragments precomputed in smem in mma lane layout: sBf[kk][nt][lane] = {b0,b1}.
__global__ void __launch_bounds__(256) k_final_mma(const float* __restrict__ W3,
                                                   const float* __restrict__ b3,
                                                   const float* __restrict__ Wfc,
                                                   const float* __restrict__ bfc,
                                                   float* __restrict__ out) {
    __shared__ __align__(16) unsigned int sBf[4 * 16 * 32 * 2];  // 16KB
    __shared__ __align__(16) float sB3[128];
    __shared__ __align__(16) float sF[128];

    int tid = threadIdx.x;
    // fill B fragments: entry (kk, nt, lane): g=lane>>2, tg=lane&3
    // b0 = {W3[k0][j], W3[k0+1][j]}, b1 = {W3[k0+8][j], W3[k0+9][j]},
    // k0 = kk*16 + 2*tg, j = nt*8 + g
    for (int idx = tid; idx < 4 * 16 * 32; idx += 256) {
        int kk = idx >> 9;
        int rem = idx & 511;
        int nt = rem >> 5;
        int lane = rem & 31;
        int g = lane >> 2, tg = lane & 3;
        int k0 = kk * 16 + 2 * tg;
        int j = nt * 8 + g;
        sBf[idx * 2 + 0] = f2h2(W3[k0 * 128 + j], W3[(k0 + 1) * 128 + j]);
        sBf[idx * 2 + 1] = f2h2(W3[(k0 + 8) * 128 + j], W3[(k0 + 9) * 128 + j]);
    }
    if (tid < 128) { sB3[tid] = b3[tid]; sF[tid] = Wfc[tid]; }
    __syncthreads();

    int wid = tid >> 5;
    int lane = tid & 31;
    int g = lane >> 2, tg = lane & 3;
    int node0 = blockIdx.x * 128 + wid * 16;
    int rowA = node0 + g;       // nodes for d0/d1
    int rowB = rowA + 8;        // nodes for d2/d3

    // preload A fragments for all 4 K-steps (16 u32)
    // a0: word kk*8+tg of rowA; a2: +4; a1/a3: same of rowB
    unsigned int aw[4][4];
    const unsigned int* pa = g_a3h + (size_t)rowA * 32;
    const unsigned int* pb = g_a3h + (size_t)rowB * 32;
#pragma unroll
    for (int kk = 0; kk < 4; kk++) {
        aw[kk][0] = (rowA < N_NODES) ? __ldg(&pa[kk * 8 + tg]) : 0u;
        aw[kk][1] = (rowB < N_NODES) ? __ldg(&pb[kk * 8 + tg]) : 0u;
        aw[kk][2] = (rowA < N_NODES) ? __ldg(&pa[kk * 8 + tg + 4]) : 0u;
        aw[kk][3] = (rowB < N_NODES) ? __ldg(&pb[kk * 8 + tg + 4]) : 0u;
    }

    float oA = 0.f, oB = 0.f;
#pragma unroll
    for (int nt = 0; nt < 16; nt++) {
        float d0 = 0.f, d1 = 0.f, d2 = 0.f, d3 = 0.f;
#pragma unroll
        for (int kk = 0; kk < 4; kk++) {
            const uint2* bp = (const uint2*)sBf;
            uint2 bf = bp[(kk * 16 + nt) * 32 + lane];
            asm volatile(
                "mma.sync.aligned.m16n8k16.row.col.f32.f16.f16.f32 "
                "{%0, %1, %2, %3}, {%4, %5, %6, %7}, {%8, %9}, {%0, %1, %2, %3};"
                : "+f"(d0), "+f"(d1), "+f"(d2), "+f"(d3)
                : "r"(aw[kk][0]), "r"(aw[kk][1]), "r"(aw[kk][2]), "r"(aw[kk][3]),
                  "r"(bf.x), "r"(bf.y));
        }
        int jj = nt * 8 + 2 * tg;
        float b0v = sB3[jj], b1v = sB3[jj + 1];
        float f0v = sF[jj],  f1v = sF[jj + 1];
        oA += fmaxf(d0 + b0v, 0.f) * f0v + fmaxf(d1 + b1v, 0.f) * f1v;
        oB += fmaxf(d2 + b0v, 0.f) * f0v + fmaxf(d3 + b1v, 0.f) * f1v;
    }
    // reduce over the 4 threads of the group (tg = 0..3)
    oA += __shfl_xor_sync(0xffffffffu, oA, 1);
    oA += __shfl_xor_sync(0xffffffffu, oA, 2);
    oB += __shfl_xor_sync(0xffffffffu, oB, 1);
    oB += __shfl_xor_sync(0xffffffffu, oB, 2);
    if (tg == 0) {
        float bf = __ldg(&bfc[0]);
        if (rowA < N_NODES) out[rowA] = oA + bf;
        if (rowB < N_NODES) out[rowB] = oB + bf;
    }
}

// ---------------- launch ----------------
extern "C" void kernel_launch(void* const* d_in, const int* in_sizes, int n_in,
                              void* d_out, int out_size) {
    const float* x   = (const float*)d_in[0];
    const void*  ei  = d_in[1];
    const float* W1  = (const float*)d_in[2];
    const float* b1  = (const float*)d_in[3];
    const float* W2  = (const float*)d_in[4];
    const float* b2  = (const float*)d_in[5];
    const float* W3  = (const float*)d_in[6];
    const float* b3  = (const float*)d_in[7];
    const float* Wfc = (const float*)d_in[8];
    const float* bfc = (const float*)d_in[9];
    float* out = (float*)d_out;

    // graph build
    k_count<<<GE, 256>>>(ei);
    k_scan<<<SCAN_NB, SCAN_B>>>();
    k_fillgemm1<<<GE + GN, 256>>>(x, W1);

    // layer 1 aggregation (fp16, 8-edge unroll)
    k_agg16h<<<(N_NODES + 127) / 128, 256>>>(b1);

    // layer 2: fused aggregate(16) + GEMM 16->64 -> fp16 h2'
    k_aggemm2<<<(N_NODES + 255) / 256, 256>>>(W2, b2);

    // layer 3: fp16 aggregate 64-wide -> fp16 a3, then HMMA GEMM + relu + FC
    k_agg64h<<<(N_NODES + 31) / 32, 256>>>();
    k_final_mma<<<(N_NODES + 127) / 128, 256>>>(W3, b3, Wfc, bfc, out);
}

// round 14
// speedup vs baseline: 1.4430x; 1.0075x over previous
#include <cuda_runtime.h>
#include <cuda_fp16.h>

// Problem constants (fixed by setup_inputs)
static constexpr int N_NODES = 100000;
static constexpr int N_EDGES = 1600000;
static constexpr int SCAN_B  = 512;
static constexpr int SCAN_NB = (N_NODES + SCAN_B - 1) / SCAN_B;  // 196
static constexpr int GE = N_EDGES / 256;          // 6250 (exact)
static constexpr int GN = (N_NODES + 255) / 256;  // 391

// ---------------- scratch (static __device__, zero-initialized) ----------------
__device__ int   g_cnt[N_NODES];               // zeroed by k_scan for next launch
__device__ int   g_row[N_NODES + 1];
__device__ int   g_blkagg[SCAN_NB];
__device__ volatile int g_blkflag[SCAN_NB];    // zeroed by k_count each launch
__device__ int   g_col[N_EDGES];
__device__ unsigned long long g_ep[N_EDGES];   // packed s(17) | d(17) | pos
__device__ float g_dinv[N_NODES];
__device__ unsigned int g_t1h[N_NODES * 8];    // fp16: dinv * (x @ W1)
__device__ unsigned int g_h1h[N_NODES * 8];    // fp16: dinv * relu(...)
__device__ unsigned int g_h2h[N_NODES * 32];   // fp16: dinv * relu(a2@W2+b2)

// ---------------- helpers ----------------
typedef unsigned long long ull;
__device__ __forceinline__ ull pack2(float v) {
    ull r; asm("mov.b64 %0, {%1, %1};" : "=l"(r) : "f"(v)); return r;
}
__device__ __forceinline__ void ffma2(ull& d, ull a, ull b) {
    asm("fma.rn.f32x2 %0, %1, %2, %0;" : "+l"(d) : "l"(a), "l"(b));
}
__device__ __forceinline__ float2 unpack2(ull v) {
    float2 r; asm("mov.b64 {%0, %1}, %2;" : "=f"(r.x), "=f"(r.y) : "l"(v)); return r;
}
__device__ __forceinline__ unsigned int hadd2u(unsigned int a, unsigned int b) {
    __half2 r = __hadd2(*(const __half2*)&a, *(const __half2*)&b);
    return *(const unsigned int*)&r;
}
__device__ __forceinline__ void acc_h2(float2& acc, unsigned int h) {
    float2 f = __half22float2(*(const __half2*)&h);
    acc.x += f.x; acc.y += f.y;
}
__device__ __forceinline__ unsigned int f2h2(float a, float b) {
    __half2 h = __floats2half2_rn(a, b);
    return *(const unsigned int*)&h;
}

// ---------------- k_count: detect + decode + degree count + pack ---------------
__global__ void __launch_bounds__(256) k_count(const void* e) {
    __shared__ int s_is64;
    int gtid = blockIdx.x * 256 + threadIdx.x;
    if (gtid < SCAN_NB) g_blkflag[gtid] = 0;   // reset for k_scan (runs after)
    if (threadIdx.x == 0) {
        const unsigned int* eu = (const unsigned int*)e;
        int is64 = 1;
#pragma unroll
        for (int k = 0; k < 16; k++)
            if (eu[2 * k + 1] != 0u) is64 = 0;
        s_is64 = is64;
    }
    __syncthreads();
    int i = gtid;
    if (i >= N_EDGES) return;
    int s, d;
    if (s_is64) {
        const long long* p = (const long long*)e;
        s = (int)p[i];
        d = (int)p[N_EDGES + i];
    } else {
        const int* p = (const int*)e;
        s = p[i];
        d = p[N_EDGES + i];
    }
    if ((unsigned)d >= (unsigned)N_NODES || (unsigned)s >= (unsigned)N_NODES) {
        g_ep[i] = ~0ull;
        return;
    }
    int pos = atomicAdd(&g_cnt[d], 1);
    g_ep[i] = (ull)(unsigned)s | ((ull)(unsigned)d << 17) | ((ull)(unsigned)pos << 34);
}

// ---------------- k_scan: exclusive scan + dinv + cnt re-zero ------------------
__global__ void __launch_bounds__(SCAN_B) k_scan() {
    __shared__ int s[SCAN_B];
    __shared__ int sPre;
    int bid = blockIdx.x;
    int i = bid * SCAN_B + threadIdx.x;
    int v = (i < N_NODES) ? g_cnt[i] : 0;
    if (i < N_NODES) {
        g_dinv[i] = rsqrtf((float)(v + 1));
        g_cnt[i] = 0;                      // restore invariant for next launch
    }
    s[threadIdx.x] = v;
    __syncthreads();
    for (int d = 1; d < SCAN_B; d <<= 1) {
        int t = (threadIdx.x >= d) ? s[threadIdx.x - d] : 0;
        __syncthreads();
        s[threadIdx.x] += t;
        __syncthreads();
    }
    if (threadIdx.x == SCAN_B - 1) {
        g_blkagg[bid] = s[SCAN_B - 1];
        __threadfence();
        g_blkflag[bid] = 1;
    }
    if (threadIdx.x == 0) sPre = 0;
    __syncthreads();
    int p = 0;
    for (int b = threadIdx.x; b < bid; b += SCAN_B) {
        while (g_blkflag[b] == 0) { }
        p += *((volatile int*)&g_blkagg[b]);
    }
    if (p) atomicAdd(&sPre, p);
    __syncthreads();
    if (i < N_NODES) g_row[i] = sPre + s[threadIdx.x] - v;
    if (bid == 0 && threadIdx.x == 0) g_row[N_NODES] = N_EDGES;
}

// ---------------- merged: CSR fill (blocks < GE) + gemm1 (blocks >= GE) --------
__global__ void __launch_bounds__(256) k_fillgemm1(const float* __restrict__ x,
                                                   const float* __restrict__ W1) {
    __shared__ __align__(16) float sW[128 * 16];
    if (blockIdx.x < GE) {
        int i = blockIdx.x * 256 + threadIdx.x;
        ull ep = g_ep[i];
        int d = (int)((ep >> 17) & 0x1FFFFull);
        if (d < N_NODES)
            g_col[g_row[d] + (int)(ep >> 34)] = (int)(ep & 0x1FFFFull);
        return;
    }
    for (int idx = threadIdx.x; idx < 128 * 16; idx += 256) sW[idx] = W1[idx];
    __syncthreads();
    int n = (blockIdx.x - GE) * 256 + threadIdx.x;
    if (n >= N_NODES) return;
    const float4* xr = (const float4*)(x + (size_t)n * 128);
    ull acc[8];
#pragma unroll
    for (int q = 0; q < 8; q++) acc[q] = 0ull;
#pragma unroll 4
    for (int k4 = 0; k4 < 32; k4++) {
        float4 v = __ldg(&xr[k4]);
#pragma unroll
        for (int kk = 0; kk < 4; kk++) {
            float xv = (kk == 0) ? v.x : (kk == 1) ? v.y : (kk == 2) ? v.z : v.w;
            ull av = pack2(xv);
            const ulonglong2* wr = (const ulonglong2*)(sW + (4 * k4 + kk) * 16);
            ulonglong2 w01 = wr[0], w23 = wr[1], w45 = wr[2], w67 = wr[3];
            ffma2(acc[0], av, w01.x); ffma2(acc[1], av, w01.y);
            ffma2(acc[2], av, w23.x); ffma2(acc[3], av, w23.y);
            ffma2(acc[4], av, w45.x); ffma2(acc[5], av, w45.y);
            ffma2(acc[6], av, w67.x); ffma2(acc[7], av, w67.y);
        }
    }
    float di = g_dinv[n];
    unsigned int hs[8];
#pragma unroll
    for (int q = 0; q < 8; q++) {
        float2 pv = unpack2(acc[q]);
        hs[q] = f2h2(di * pv.x, di * pv.y);
    }
    uint4* o = (uint4*)(g_t1h + (size_t)n * 8);
    o[0] = make_uint4(hs[0], hs[1], hs[2], hs[3]);
    o[1] = make_uint4(hs[4], hs[5], hs[6], hs[7]);
}

// ---------------- agg 16-wide fp16 (+b1+relu), 8-edge unroll for MLP -----------
__global__ void __launch_bounds__(256) k_agg16h(const float* __restrict__ bias) {
    const uint4* __restrict__ t = (const uint4*)g_t1h;  // 2 uint4 per node
    int g = threadIdx.x & 1;
    int i = blockIdx.x * 128 + (threadIdx.x >> 1);
    if (i >= N_NODES) return;

    float2 a0 = make_float2(0.f, 0.f), a1 = a0, a2 = a0, a3 = a0;
    {
        uint4 sv = __ldg(&t[(size_t)i * 2 + g]);   // self loop
        acc_h2(a0, sv.x); acc_h2(a1, sv.y); acc_h2(a2, sv.z); acc_h2(a3, sv.w);
    }
    int beg = g_row[i], end = g_row[i + 1];
    int j = beg;
    for (; j + 7 < end; j += 8) {
        int s0 = __ldg(&g_col[j]);
        int s1 = __ldg(&g_col[j + 1]);
        int s2 = __ldg(&g_col[j + 2]);
        int s3 = __ldg(&g_col[j + 3]);
        int s4 = __ldg(&g_col[j + 4]);
        int s5 = __ldg(&g_col[j + 5]);
        int s6 = __ldg(&g_col[j + 6]);
        int s7 = __ldg(&g_col[j + 7]);
        uint4 v0 = __ldg(&t[(size_t)s0 * 2 + g]);
        uint4 v1 = __ldg(&t[(size_t)s1 * 2 + g]);
        uint4 v2 = __ldg(&t[(size_t)s2 * 2 + g]);
        uint4 v3 = __ldg(&t[(size_t)s3 * 2 + g]);
        uint4 v4 = __ldg(&t[(size_t)s4 * 2 + g]);
        uint4 v5 = __ldg(&t[(size_t)s5 * 2 + g]);
        uint4 v6 = __ldg(&t[(size_t)s6 * 2 + g]);
        uint4 v7 = __ldg(&t[(size_t)s7 * 2 + g]);
        acc_h2(a0, hadd2u(v0.x, v1.x)); acc_h2(a0, hadd2u(v2.x, v3.x));
        acc_h2(a0, hadd2u(v4.x, v5.x)); acc_h2(a0, hadd2u(v6.x, v7.x));
        acc_h2(a1, hadd2u(v0.y, v1.y)); acc_h2(a1, hadd2u(v2.y, v3.y));
        acc_h2(a1, hadd2u(v4.y, v5.y)); acc_h2(a1, hadd2u(v6.y, v7.y));
        acc_h2(a2, hadd2u(v0.z, v1.z)); acc_h2(a2, hadd2u(v2.z, v3.z));
        acc_h2(a2, hadd2u(v4.z, v5.z)); acc_h2(a2, hadd2u(v6.z, v7.z));
        acc_h2(a3, hadd2u(v0.w, v1.w)); acc_h2(a3, hadd2u(v2.w, v3.w));
        acc_h2(a3, hadd2u(v4.w, v5.w)); acc_h2(a3, hadd2u(v6.w, v7.w));
    }
    for (; j + 1 < end; j += 2) {
        int s0 = __ldg(&g_col[j]);
        int s1 = __ldg(&g_col[j + 1]);
        uint4 v0 = __ldg(&t[(size_t)s0 * 2 + g]);
        uint4 v1 = __ldg(&t[(size_t)s1 * 2 + g]);
        acc_h2(a0, hadd2u(v0.x, v1.x));
        acc_h2(a1, hadd2u(v0.y, v1.y));
        acc_h2(a2, hadd2u(v0.z, v1.z));
        acc_h2(a3, hadd2u(v0.w, v1.w));
    }
    if (j < end) {
        int s = __ldg(&g_col[j]);
        uint4 v = __ldg(&t[(size_t)s * 2 + g]);
        acc_h2(a0, v.x); acc_h2(a1, v.y); acc_h2(a2, v.z); acc_h2(a3, v.w);
    }
    float di = g_dinv[i];
    float d2 = di * di;
    const float2* b2 = (const float2*)bias;
    float2 bv0 = b2[4 * g + 0], bv1 = b2[4 * g + 1];
    float2 bv2 = b2[4 * g + 2], bv3 = b2[4 * g + 3];
    unsigned int h0 = f2h2(fmaxf(fmaf(d2, a0.x, di * bv0.x), 0.f),
                           fmaxf(fmaf(d2, a0.y, di * bv0.y), 0.f));
    unsigned int h1 = f2h2(fmaxf(fmaf(d2, a1.x, di * bv1.x), 0.f),
                           fmaxf(fmaf(d2, a1.y, di * bv1.y), 0.f));
    unsigned int h2 = f2h2(fmaxf(fmaf(d2, a2.x, di * bv2.x), 0.f),
                           fmaxf(fmaf(d2, a2.y, di * bv2.y), 0.f));
    unsigned int h3 = f2h2(fmaxf(fmaf(d2, a3.x, di * bv3.x), 0.f),
                           fmaxf(fmaf(d2, a3.y, di * bv3.y), 0.f));
    ((uint4*)(g_h1h + (size_t)i * 8))[g] = make_uint4(h0, h1, h2, h3);
}

// ---------------- fused: agg(h1',16) -> GEMM 16->64 -> fp16 h2' ----------------
__global__ void __launch_bounds__(256) k_aggemm2(const float* __restrict__ W2,
                                                 const float* __restrict__ b2) {
    __shared__ float sA[256][17];
    __shared__ __align__(16) float sW[16 * 64];
    __shared__ __align__(16) float sB[64];
    for (int idx = threadIdx.x; idx < 16 * 64; idx += 256) sW[idx] = W2[idx];
    if (threadIdx.x < 64) sB[threadIdx.x] = b2[threadIdx.x];
    __syncthreads();

    const uint4* __restrict__ t = (const uint4*)g_h1h;
    int nodeBase = blockIdx.x * 256;
    int g = threadIdx.x & 1;
#pragma unroll 1
    for (int pass = 0; pass < 2; pass++) {
        int local = pass * 128 + (threadIdx.x >> 1);
        int i = nodeBase + local;
        if (i < N_NODES) {
            float2 a0 = make_float2(0.f, 0.f), a1 = a0, a2 = a0, a3 = a0;
            {
                uint4 sv = __ldg(&t[(size_t)i * 2 + g]);
                acc_h2(a0, sv.x); acc_h2(a1, sv.y); acc_h2(a2, sv.z); acc_h2(a3, sv.w);
            }
            int beg = g_row[i], end = g_row[i + 1];
            int j = beg;
            for (; j + 3 < end; j += 4) {
                int s0 = __ldg(&g_col[j]);
                int s1 = __ldg(&g_col[j + 1]);
                int s2 = __ldg(&g_col[j + 2]);
                int s3 = __ldg(&g_col[j + 3]);
                uint4 v0 = __ldg(&t[(size_t)s0 * 2 + g]);
                uint4 v1 = __ldg(&t[(size_t)s1 * 2 + g]);
                uint4 v2 = __ldg(&t[(size_t)s2 * 2 + g]);
                uint4 v3 = __ldg(&t[(size_t)s3 * 2 + g]);
                acc_h2(a0, hadd2u(v0.x, v1.x)); acc_h2(a0, hadd2u(v2.x, v3.x));
                acc_h2(a1, hadd2u(v0.y, v1.y)); acc_h2(a1, hadd2u(v2.y, v3.y));
                acc_h2(a2, hadd2u(v0.z, v1.z)); acc_h2(a2, hadd2u(v2.z, v3.z));
                acc_h2(a3, hadd2u(v0.w, v1.w)); acc_h2(a3, hadd2u(v2.w, v3.w));
            }
            if (j + 1 < end) {
                int s0 = __ldg(&g_col[j]);
                int s1 = __ldg(&g_col[j + 1]);
                uint4 v0 = __ldg(&t[(size_t)s0 * 2 + g]);
                uint4 v1 = __ldg(&t[(size_t)s1 * 2 + g]);
                acc_h2(a0, hadd2u(v0.x, v1.x));
                acc_h2(a1, hadd2u(v0.y, v1.y));
                acc_h2(a2, hadd2u(v0.z, v1.z));
                acc_h2(a3, hadd2u(v0.w, v1.w));
                j += 2;
            }
            if (j < end) {
                int s = __ldg(&g_col[j]);
                uint4 v = __ldg(&t[(size_t)s * 2 + g]);
                acc_h2(a0, v.x); acc_h2(a1, v.y); acc_h2(a2, v.z); acc_h2(a3, v.w);
            }
            float di = g_dinv[i];
            float* row = &sA[local][g * 8];
            row[0] = di * a0.x; row[1] = di * a0.y;
            row[2] = di * a1.x; row[3] = di * a1.y;
            row[4] = di * a2.x; row[5] = di * a2.y;
            row[6] = di * a3.x; row[7] = di * a3.y;
        }
    }
    __syncthreads();

    int n = nodeBase + threadIdx.x;
    if (n >= N_NODES) return;
    float a[16];
#pragma unroll
    for (int k = 0; k < 16; k++) a[k] = sA[threadIdx.x][k];
    float di = g_dinv[n];

#pragma unroll
    for (int c = 0; c < 4; c++) {
        ull acc[8];
        const ull* sBu = (const ull*)sB;
#pragma unroll
        for (int m = 0; m < 8; m++) acc[m] = sBu[c * 8 + m];
#pragma unroll
        for (int k = 0; k < 16; k++) {
            ull av = pack2(a[k]);
            const ull* wr = (const ull*)(sW + k * 64) + c * 8;
#pragma unroll
            for (int m = 0; m < 8; m++) ffma2(acc[m], av, wr[m]);
        }
        unsigned int hs[8];
#pragma unroll
        for (int m = 0; m < 8; m++) {
            float2 pv = unpack2(acc[m]);
            hs[m] = f2h2(fmaxf(di * pv.x, 0.f), fmaxf(di * pv.y, 0.f));
        }
        uint4* o = (uint4*)(g_h2h + (size_t)n * 32 + c * 8);
        o[0] = make_uint4(hs[0], hs[1], hs[2], hs[3]);
        o[1] = make_uint4(hs[4], hs[5], hs[6], hs[7]);
    }
}

// ---------------- merged: agg64(h2') -> smem a3 -> HMMA layer3 + FC ------------
// Block: 256 threads, 128 nodes. Phase A: B fragments + agg (8 thr/node, 4
// passes) into smem (stride-33 pad -> conflict-free). Phase B: m16n8k16 HMMA.
__global__ void __launch_bounds__(256) k_agg64_final(const float* __restrict__ W3,
                                                     const float* __restrict__ b3,
                                                     const float* __restrict__ Wfc,
                                                     const float* __restrict__ bfc,
                                                     float* __restrict__ out) {
    __shared__ __align__(16) unsigned int sBf[4 * 16 * 32 * 2];  // 16KB
    __shared__ __align__(16) unsigned int sA3[128][33];          // 16.5KB fp16 a3
    __shared__ __align__(16) float sB3[128];
    __shared__ __align__(16) float sF[128];

    int tid = threadIdx.x;
    // B fragments: entry (kk, nt, lane): g=lane>>2, tg=lane&3
    for (int idx = tid; idx < 4 * 16 * 32; idx += 256) {
        int kk = idx >> 9;
        int rem = idx & 511;
        int nt = rem >> 5;
        int lane = rem & 31;
        int g = lane >> 2, tg = lane & 3;
        int k0 = kk * 16 + 2 * tg;
        int j = nt * 8 + g;
        sBf[idx * 2 + 0] = f2h2(W3[k0 * 128 + j], W3[(k0 + 1) * 128 + j]);
        sBf[idx * 2 + 1] = f2h2(W3[(k0 + 8) * 128 + j], W3[(k0 + 9) * 128 + j]);
    }
    if (tid < 128) { sB3[tid] = b3[tid]; sF[tid] = Wfc[tid]; }

    // ---- Phase A: aggregate 64-wide fp16 for this block's 128 nodes
    const uint4* __restrict__ t = (const uint4*)g_h2h;
    int ga = tid & 7;                       // uint4 slot within row
    int nodeBase = blockIdx.x * 128;
#pragma unroll 1
    for (int pass = 0; pass < 4; pass++) {
        int local = pass * 32 + (tid >> 3);
        int i = nodeBase + local;
        float2 a0 = make_float2(0.f, 0.f), a1 = a0, a2 = a0, a3 = a0;
        if (i < N_NODES) {
            {
                uint4 sv = __ldg(&t[(size_t)i * 8 + ga]);   // self loop
                acc_h2(a0, sv.x); acc_h2(a1, sv.y); acc_h2(a2, sv.z); acc_h2(a3, sv.w);
            }
            int beg = g_row[i], end = g_row[i + 1];
            int j = beg;
            for (; j + 3 < end; j += 4) {
                int s0 = __ldg(&g_col[j]);
                int s1 = __ldg(&g_col[j + 1]);
                int s2 = __ldg(&g_col[j + 2]);
                int s3 = __ldg(&g_col[j + 3]);
                uint4 v0 = __ldg(&t[(size_t)s0 * 8 + ga]);
                uint4 v1 = __ldg(&t[(size_t)s1 * 8 + ga]);
                uint4 v2 = __ldg(&t[(size_t)s2 * 8 + ga]);
                uint4 v3 = __ldg(&t[(size_t)s3 * 8 + ga]);
                acc_h2(a0, hadd2u(v0.x, v1.x)); acc_h2(a0, hadd2u(v2.x, v3.x));
                acc_h2(a1, hadd2u(v0.y, v1.y)); acc_h2(a1, hadd2u(v2.y, v3.y));
                acc_h2(a2, hadd2u(v0.z, v1.z)); acc_h2(a2, hadd2u(v2.z, v3.z));
                acc_h2(a3, hadd2u(v0.w, v1.w)); acc_h2(a3, hadd2u(v2.w, v3.w));
            }
            if (j + 1 < end) {
                int s0 = __ldg(&g_col[j]);
                int s1 = __ldg(&g_col[j + 1]);
                uint4 v0 = __ldg(&t[(size_t)s0 * 8 + ga]);
                uint4 v1 = __ldg(&t[(size_t)s1 * 8 + ga]);
                acc_h2(a0, hadd2u(v0.x, v1.x));
                acc_h2(a1, hadd2u(v0.y, v1.y));
                acc_h2(a2, hadd2u(v0.z, v1.z));
                acc_h2(a3, hadd2u(v0.w, v1.w));
                j += 2;
            }
            if (j < end) {
                int s = __ldg(&g_col[j]);
                uint4 v = __ldg(&t[(size_t)s * 8 + ga]);
                acc_h2(a0, v.x); acc_h2(a1, v.y); acc_h2(a2, v.z); acc_h2(a3, v.w);
            }
        }
        float di = (i < N_NODES) ? g_dinv[i] : 0.f;
        unsigned int* rp = &sA3[local][ga * 4];
        rp[0] = f2h2(di * a0.x, di * a0.y);
        rp[1] = f2h2(di * a1.x, di * a1.y);
        rp[2] = f2h2(di * a2.x, di * a2.y);
        rp[3] = f2h2(di * a3.x, di * a3.y);
    }
    __syncthreads();

    // ---- Phase B: HMMA. Warp w owns nodes [16w, 16w+16) of this block.
    int wid = tid >> 5;
    int lane = tid & 31;
    int g = lane >> 2, tg = lane & 3;
    int rA = wid * 16 + g;       // local rows
    int rB = rA + 8;
    int rowA = nodeBase + rA;
    int rowB = nodeBase + rB;

    unsigned int aw[4][4];
#pragma unroll
    for (int kk = 0; kk < 4; kk++) {
        aw[kk][0] = sA3[rA][kk * 8 + tg];
        aw[kk][1] = sA3[rB][kk * 8 + tg];
        aw[kk][2] = sA3[rA][kk * 8 + tg + 4];
        aw[kk][3] = sA3[rB][kk * 8 + tg + 4];
    }

    float oA = 0.f, oB = 0.f;
#pragma unroll
    for (int nt = 0; nt < 16; nt++) {
        float d0 = 0.f, d1 = 0.f, d2 = 0.f, d3 = 0.f;
#pragma unroll
        for (int kk = 0; kk < 4; kk++) {
            const uint2* bp = (const uint2*)sBf;
            uint2 bf = bp[(kk * 16 + nt) * 32 + lane];
            asm volatile(
                "mma.sync.aligned.m16n8k16.row.col.f32.f16.f16.f32 "
                "{%0, %1, %2, %3}, {%4, %5, %6, %7}, {%8, %9}, {%0, %1, %2, %3};"
                : "+f"(d0), "+f"(d1), "+f"(d2), "+f"(d3)
                : "r"(aw[kk][0]), "r"(aw[kk][1]), "r"(aw[kk][2]), "r"(aw[kk][3]),
                  "r"(bf.x), "r"(bf.y));
        }
        int jj = nt * 8 + 2 * tg;
        float b0v = sB3[jj], b1v = sB3[jj + 1];
        float f0v = sF[jj],  f1v = sF[jj + 1];
        oA += fmaxf(d0 + b0v, 0.f) * f0v + fmaxf(d1 + b1v, 0.f) * f1v;
        oB += fmaxf(d2 + b0v, 0.f) * f0v + fmaxf(d3 + b1v, 0.f) * f1v;
    }
    oA += __shfl_xor_sync(0xffffffffu, oA, 1);
    oA += __shfl_xor_sync(0xffffffffu, oA, 2);
    oB += __shfl_xor_sync(0xffffffffu, oB, 1);
    oB += __shfl_xor_sync(0xffffffffu, oB, 2);
    if (tg == 0) {
        float bf = __ldg(&bfc[0]);
        if (rowA < N_NODES) out[rowA] = oA + bf;
        if (rowB < N_NODES) out[rowB] = oB + bf;
    }
}

// ---------------- launch ----------------
extern "C" void kernel_launch(void* const* d_in, const int* in_sizes, int n_in,
                              void* d_out, int out_size) {
    const float* x   = (const float*)d_in[0];
    const void*  ei  = d_in[1];
    const float* W1  = (const float*)d_in[2];
    const float* b1  = (const float*)d_in[3];
    const float* W2  = (const float*)d_in[4];
    const float* b2  = (const float*)d_in[5];
    const float* W3  = (const float*)d_in[6];
    const float* b3  = (const float*)d_in[7];
    const float* Wfc = (const float*)d_in[8];
    const float* bfc = (const float*)d_in[9];
    float* out = (float*)d_out;

    // graph build
    k_count<<<GE, 256>>>(ei);
    k_scan<<<SCAN_NB, SCAN_B>>>();
    k_fillgemm1<<<GE + GN, 256>>>(x, W1);

    // layer 1 aggregation (fp16, 8-edge unroll)
    k_agg16h<<<(N_NODES + 127) / 128, 256>>>(b1);

    // layer 2: fused aggregate(16) + GEMM 16->64 -> fp16 h2'
    k_aggemm2<<<(N_NODES + 255) / 256, 256>>>(W2, b2);

    // layer 3: fused agg64 + HMMA GEMM + relu + FC (a3 lives in smem)
    k_agg64_final<<<(N_NODES + 127) / 128, 256>>>(W3, b3, Wfc, bfc, out);
}